// round 2
// baseline (speedup 1.0000x reference)
#include <cuda_runtime.h>
#include <cuda_bf16.h>
#include <math.h>

#define BS 32
#define NQ 900
#define NC 91
#define NT 30
#define NTT (BS * NT)   // 960 columns of C

// Transposed per-batch cost slice: g_slice[b][t][q] = C[b, q, b*NT + t]
__device__ float g_slice[BS * NT * NQ];

// ---------------------------------------------------------------------------
// Cost matrix: 8 rows per block (one warp per row), 256 threads.
// ---------------------------------------------------------------------------
#define RPB 8

__global__ __launch_bounds__(256) void cost_kernel(
    const float* __restrict__ logits,   // (BS, NQ, NC)
    const float* __restrict__ boxes,    // (BS, NQ, 4) cxcywh
    const int*   __restrict__ labels,   // (BS, NT)
    const float* __restrict__ tboxes,   // (BS, NT, 4) cxcywh
    float* __restrict__ C)              // (BS*NQ, NTT)
{
    __shared__ int    slab[NTT];
    __shared__ float4 stb[NTT];
    __shared__ float  sprob[RPB][NC + 1];

    const int tid  = threadIdx.x;
    const int warp = tid >> 5;
    const int lane = tid & 31;

    // stage all 960 targets once per block
    for (int j = tid; j < NTT; j += 256) {
        slab[j] = labels[j];
        stb[j]  = reinterpret_cast<const float4*>(tboxes)[j];
    }
    __syncthreads();

    const int row = blockIdx.x * RPB + warp;   // grid = 3600 exactly
    const int b   = row / NQ;
    const int q   = row - b * NQ;

    // ---- warp softmax over 91 classes (lanes hold idx l, l+32, l+64) ----
    const float* lrow = logits + (size_t)row * NC;
    const float v0 = lrow[lane];
    const float v1 = lrow[lane + 32];
    const float v2 = (lane < NC - 64) ? lrow[lane + 64] : -INFINITY;
    float m = fmaxf(fmaxf(v0, v1), v2);
    #pragma unroll
    for (int o = 16; o; o >>= 1) m = fmaxf(m, __shfl_xor_sync(~0u, m, o));
    const float e0 = expf(v0 - m);
    const float e1 = expf(v1 - m);
    const float e2 = (lane < NC - 64) ? expf(v2 - m) : 0.0f;
    float s = e0 + e1 + e2;
    #pragma unroll
    for (int o = 16; o; o >>= 1) s += __shfl_xor_sync(~0u, s, o);
    const float inv = 1.0f / s;
    sprob[warp][lane]      = e0 * inv;
    sprob[warp][lane + 32] = e1 * inv;
    if (lane < NC - 64) sprob[warp][lane + 64] = e2 * inv;
    __syncwarp();

    // ---- own box ----
    const float4 pb = reinterpret_cast<const float4*>(boxes)[row];
    const float cx = pb.x, cy = pb.y, w = pb.z, h = pb.w;
    const float ax0 = cx - 0.5f * w, ay0 = cy - 0.5f * h;
    const float ax1 = cx + 0.5f * w, ay1 = cy + 0.5f * h;
    const float areaA = (ax1 - ax0) * (ay1 - ay0);

    float* __restrict__ crow = C + (size_t)row * NTT;
    const int tlo = b * NT;

    #pragma unroll 5
    for (int k = 0; k < 30; k++) {
        const int j = lane + 32 * k;          // 32*30 == 960: full coverage
        const int lab = slab[j];
        const float4 tb = stb[j];

        const float cost_class = 1.0f - sprob[warp][lab];
        const float l1 = fabsf(cx - tb.x) + fabsf(cy - tb.y)
                       + fabsf(w - tb.z) + fabsf(h - tb.w);

        const float bx0 = tb.x - 0.5f * tb.z, by0 = tb.y - 0.5f * tb.w;
        const float bx1 = tb.x + 0.5f * tb.z, by1 = tb.y + 0.5f * tb.w;
        const float areaB = (bx1 - bx0) * (by1 - by0);

        const float ix0 = fmaxf(ax0, bx0), iy0 = fmaxf(ay0, by0);
        const float ix1 = fminf(ax1, bx1), iy1 = fminf(ay1, by1);
        const float iw = fmaxf(ix1 - ix0, 0.0f), ih = fmaxf(iy1 - iy0, 0.0f);
        const float inter = iw * ih;
        const float uni = areaA + areaB - inter;
        const float iou = inter / uni;

        const float ex0 = fminf(ax0, bx0), ey0 = fminf(ay0, by0);
        const float ex1 = fmaxf(ax1, bx1), ey1 = fmaxf(ay1, by1);
        const float encl = fmaxf(ex1 - ex0, 0.0f) * fmaxf(ey1 - ey0, 0.0f);
        const float giou = iou - (encl - uni) / encl;

        const float c = 5.0f * l1 + cost_class + 2.0f * (1.0f - giou);
        crow[j] = c;

        const int t = j - tlo;
        if ((unsigned)t < NT)
            g_slice[((size_t)tlo + t) * NQ + q] = c;
    }
}

// ---------------------------------------------------------------------------
// JV Hungarian — ONE WARP per batch, warp-synchronous, state in registers.
// Exact float64 replica of the numpy reference (tie-break = lowest index).
// Lane l owns columns j-1 = l + 32*k, k = 0..28.
// ---------------------------------------------------------------------------
#define CPL 29

__global__ __launch_bounds__(32) void lsa_kernel(
    float* __restrict__ outPred,   // (BS, NT)
    float* __restrict__ outTgt)    // (BS, NT)
{
    const int b    = blockIdx.x;
    const int lane = threadIdx.x;
    const float* __restrict__ cost = g_slice + (size_t)b * NT * NQ;
    const double DINF = 1e18;

    __shared__ double u[NT + 1];
    __shared__ int    p[NQ + 1];
    __shared__ int    way[NQ + 1];

    double v[CPL], minv[CPL];

    for (int j = lane; j <= NQ; j += 32) p[j] = 0;
    #pragma unroll
    for (int k = 0; k < CPL; k++) v[k] = 0.0;
    if (lane <= NT) u[lane] = 0.0;
    __syncwarp();

    for (int i = 1; i <= NT; i++) {
        if (lane == 0) p[0] = i;
        #pragma unroll
        for (int k = 0; k < CPL; k++) minv[k] = DINF;
        unsigned used = 0;
        int j0 = 0;
        __syncwarp();

        while (true) {
            int i0;
            if (j0 > 0) {
                if (lane == ((j0 - 1) & 31)) used |= 1u << ((j0 - 1) >> 5);
                i0 = p[j0];
            } else {
                i0 = i;
            }
            const double ui0 = u[i0];
            const float* __restrict__ crow = cost + (size_t)(i0 - 1) * NQ;

            // scan: update minv on unused owned columns; per-lane argmin
            double bv = DINF;
            int    bi = NQ + 1;
            #pragma unroll
            for (int k = 0; k < CPL; k++) {
                const int jm1 = lane + 32 * k;
                if (jm1 < NQ && !((used >> k) & 1u)) {
                    const double cur = (double)crow[jm1] - ui0 - v[k];
                    if (cur < minv[k]) { minv[k] = cur; way[jm1 + 1] = j0; }
                    if (minv[k] < bv)  { bv = minv[k]; bi = jm1 + 1; }
                }
            }
            // warp argmin with lowest-index tie-break
            #pragma unroll
            for (int o = 16; o; o >>= 1) {
                const double ov = __shfl_down_sync(~0u, bv, o);
                const int    oi = __shfl_down_sync(~0u, bi, o);
                if (ov < bv || (ov == bv && oi < bi)) { bv = ov; bi = oi; }
            }
            const double delta = __shfl_sync(~0u, bv, 0);
            const int    j1    = __shfl_sync(~0u, bi, 0);

            // dual update: used cols -> u[p[j]] += delta, v -= delta; else minv shift
            if (lane == 0) u[i] += delta;          // column 0 (p[0] == i)
            #pragma unroll
            for (int k = 0; k < CPL; k++) {
                const int jm1 = lane + 32 * k;
                if (jm1 < NQ) {
                    if ((used >> k) & 1u) { u[p[jm1 + 1]] += delta; v[k] -= delta; }
                    else                  { minv[k] -= delta; }
                }
            }
            __syncwarp();

            j0 = j1;
            if (p[j0] == 0) break;
        }

        // augment (serial on lane 0)
        if (lane == 0) {
            int jj = j0;
            while (jj) {
                const int jn = way[jj];
                p[jj] = p[jn];
                jj = jn;
            }
        }
        __syncwarp();
    }

    // extract + stable argsort by pred index (indices distinct)
    if (lane == 0) {
        int preds[NT];
        for (int j = 1; j <= NQ; j++)
            if (p[j] > 0) preds[p[j] - 1] = j - 1;

        int order[NT];
        for (int k = 0; k < NT; k++) order[k] = k;
        for (int a = 1; a < NT; a++) {
            const int o = order[a];
            const int key = preds[o];
            int c = a - 1;
            while (c >= 0 && preds[order[c]] > key) { order[c + 1] = order[c]; c--; }
            order[c + 1] = o;
        }
        for (int k = 0; k < NT; k++) {
            outPred[b * NT + k] = (float)preds[order[k]];
            outTgt[b * NT + k]  = (float)order[k];
        }
    }
}

// ---------------------------------------------------------------------------
extern "C" void kernel_launch(void* const* d_in, const int* in_sizes, int n_in,
                              void* d_out, int out_size)
{
    const float* logits = (const float*)d_in[0];   // (32,900,91) f32
    const float* boxes  = (const float*)d_in[1];   // (32,900,4)  f32
    const int*   labels = (const int*)d_in[2];     // (32,30)     i32
    const float* tboxes = (const float*)d_in[3];   // (32,30,4)   f32

    float* out = (float*)d_out;
    float* outC    = out;                                  // 32*900*960
    float* outPred = out + (size_t)BS * NQ * NTT;          // 960
    float* outTgt  = outPred + BS * NT;                    // 960

    cost_kernel<<<(BS * NQ) / RPB, 256>>>(logits, boxes, labels, tboxes, outC);
    lsa_kernel<<<BS, 32>>>(outPred, outTgt);
}

// round 3
// speedup vs baseline: 2.5139x; 2.5139x over previous
#include <cuda_runtime.h>
#include <cuda_bf16.h>
#include <math.h>

#define BS 32
#define NQ 900
#define NC 91
#define NT 30
#define NTT (BS * NT)   // 960 columns of C

// Transposed per-batch cost slice: g_slice[b][t][q] = C[b, q, b*NT + t]
__device__ float g_slice[BS * NT * NQ];

// ---------------------------------------------------------------------------
// Cost kernel: 16 rows per block (2 rows per warp), 256 threads, float4 I/O.
// ---------------------------------------------------------------------------
struct RowCtx {
    float cx, cy, w, h, ax0, ay0, ax1, ay1, areaA;
    const float* prob;
};

__device__ __forceinline__ float cost_one(const RowCtx& R, int lab,
                                          float tx, float ty, float td, float te)
{
    const float cc = 1.0f - R.prob[lab];
    const float l1 = fabsf(R.cx - tx) + fabsf(R.cy - ty)
                   + fabsf(R.w - td) + fabsf(R.h - te);
    const float bx0 = tx - 0.5f * td, by0 = ty - 0.5f * te;
    const float bx1 = tx + 0.5f * td, by1 = ty + 0.5f * te;
    const float areaB = (bx1 - bx0) * (by1 - by0);
    const float iw = fmaxf(fminf(R.ax1, bx1) - fmaxf(R.ax0, bx0), 0.0f);
    const float ih = fmaxf(fminf(R.ay1, by1) - fmaxf(R.ay0, by0), 0.0f);
    const float inter = iw * ih;
    const float uni = R.areaA + areaB - inter;
    const float iou = inter / uni;
    const float ew = fmaxf(fmaxf(R.ax1, bx1) - fminf(R.ax0, bx0), 0.0f);
    const float eh = fmaxf(fmaxf(R.ay1, by1) - fminf(R.ay0, by0), 0.0f);
    const float encl = ew * eh;
    const float giou = iou - (encl - uni) / encl;
    return 5.0f * l1 + cc + 2.0f * (1.0f - giou);
}

__device__ __forceinline__ RowCtx make_ctx(float4 pb, const float* prob)
{
    RowCtx R;
    R.cx = pb.x; R.cy = pb.y; R.w = pb.z; R.h = pb.w;
    R.ax0 = pb.x - 0.5f * pb.z; R.ay0 = pb.y - 0.5f * pb.w;
    R.ax1 = pb.x + 0.5f * pb.z; R.ay1 = pb.y + 0.5f * pb.w;
    R.areaA = (R.ax1 - R.ax0) * (R.ay1 - R.ay0);
    R.prob = prob;
    return R;
}

__global__ __launch_bounds__(256) void cost_kernel(
    const float* __restrict__ logits,   // (BS, NQ, NC)
    const float* __restrict__ boxes,    // (BS, NQ, 4)
    const int*   __restrict__ labels,   // (BS, NT)
    const float* __restrict__ tboxes,   // (BS, NT, 4)
    float* __restrict__ C)              // (BS*NQ, NTT)
{
    __shared__ alignas(16) int   slab[NTT];
    __shared__ alignas(16) float tcx[NTT], tcy[NTT], tw_[NTT], th_[NTT];
    __shared__ float sprob[16][NC + 1];

    const int tid  = threadIdx.x;
    const int warp = tid >> 5;
    const int lane = tid & 31;

    for (int j = tid; j < NTT; j += 256) {
        const float4 tb = reinterpret_cast<const float4*>(tboxes)[j];
        slab[j] = labels[j];
        tcx[j] = tb.x; tcy[j] = tb.y; tw_[j] = tb.z; th_[j] = tb.w;
    }
    __syncthreads();

    const int rbase = blockIdx.x * 16 + warp * 2;   // grid = 1800 exactly

    // ---- warp softmax for both rows ----
    #pragma unroll
    for (int rr = 0; rr < 2; rr++) {
        const int row = rbase + rr;
        const float* lrow = logits + (size_t)row * NC;
        const float v0 = lrow[lane];
        const float v1 = lrow[lane + 32];
        const float v2 = (lane < NC - 64) ? lrow[lane + 64] : -INFINITY;
        float m = fmaxf(fmaxf(v0, v1), v2);
        #pragma unroll
        for (int o = 16; o; o >>= 1) m = fmaxf(m, __shfl_xor_sync(~0u, m, o));
        const float e0 = expf(v0 - m);
        const float e1 = expf(v1 - m);
        const float e2 = (lane < NC - 64) ? expf(v2 - m) : 0.0f;
        float s = e0 + e1 + e2;
        #pragma unroll
        for (int o = 16; o; o >>= 1) s += __shfl_xor_sync(~0u, s, o);
        const float inv = 1.0f / s;
        sprob[warp * 2 + rr][lane]      = e0 * inv;
        sprob[warp * 2 + rr][lane + 32] = e1 * inv;
        if (lane < NC - 64) sprob[warp * 2 + rr][lane + 64] = e2 * inv;
    }
    __syncwarp();

    const int row0 = rbase, row1 = rbase + 1;
    const RowCtx R0 = make_ctx(reinterpret_cast<const float4*>(boxes)[row0], sprob[warp * 2]);
    const RowCtx R1 = make_ctx(reinterpret_cast<const float4*>(boxes)[row1], sprob[warp * 2 + 1]);

    float* __restrict__ c0 = C + (size_t)row0 * NTT;
    float* __restrict__ c1 = C + (size_t)row1 * NTT;

    #pragma unroll
    for (int k = 0; k < 8; k++) {
        const int idx = lane + 32 * k;       // float4 group, 240 total
        if (idx < NTT / 4) {
            const float4 X = *reinterpret_cast<const float4*>(&tcx[4 * idx]);
            const float4 Y = *reinterpret_cast<const float4*>(&tcy[4 * idx]);
            const float4 W = *reinterpret_cast<const float4*>(&tw_[4 * idx]);
            const float4 H = *reinterpret_cast<const float4*>(&th_[4 * idx]);
            const int4   L = *reinterpret_cast<const int4*>(&slab[4 * idx]);
            float4 o0, o1;
            o0.x = cost_one(R0, L.x, X.x, Y.x, W.x, H.x);
            o0.y = cost_one(R0, L.y, X.y, Y.y, W.y, H.y);
            o0.z = cost_one(R0, L.z, X.z, Y.z, W.z, H.z);
            o0.w = cost_one(R0, L.w, X.w, Y.w, W.w, H.w);
            o1.x = cost_one(R1, L.x, X.x, Y.x, W.x, H.x);
            o1.y = cost_one(R1, L.y, X.y, Y.y, W.y, H.y);
            o1.z = cost_one(R1, L.z, X.z, Y.z, W.z, H.z);
            o1.w = cost_one(R1, L.w, X.w, Y.w, W.w, H.w);
            *reinterpret_cast<float4*>(&c0[4 * idx]) = o0;
            *reinterpret_cast<float4*>(&c1[4 * idx]) = o1;
        }
    }

    // ---- scatter own-batch slice (transposed) for the LSA pass ----
    if (lane < NT) {
        {
            const int b = row0 / NQ, q = row0 - b * NQ, t = b * NT + lane;
            g_slice[(size_t)t * NQ + q] =
                cost_one(R0, slab[t], tcx[t], tcy[t], tw_[t], th_[t]);
        }
        {
            const int b = row1 / NQ, q = row1 - b * NQ, t = b * NT + lane;
            g_slice[(size_t)t * NQ + q] =
                cost_one(R1, slab[t], tcx[t], tcy[t], tw_[t], th_[t]);
        }
    }
}

// ---------------------------------------------------------------------------
// JV Hungarian, deferred-dual formulation. One block (256 thr) per batch.
// Exact ordering replica of the reference (offset-invariant comparisons,
// lowest-index tie-break). fp64 throughout.
// ---------------------------------------------------------------------------
#define LTH 256
#define LK  4    // columns per thread: jm1 = tid + 256*k

__global__ __launch_bounds__(LTH) void lsa_kernel(
    float* __restrict__ outPred,   // (BS, NT)
    float* __restrict__ outTgt)    // (BS, NT)
{
    const int b    = blockIdx.x;
    const int tid  = threadIdx.x;
    const int lane = tid & 31;
    const int warp = tid >> 5;
    const float* __restrict__ cost = g_slice + (size_t)b * NT * NQ;
    const double DINF = 1e18;

    __shared__ double u[NT + 1];
    __shared__ double v[NQ];        // index jm1 (0-based column)
    __shared__ int    way[NQ];      // 1-based predecessor column (0 = root)
    __shared__ int    p[NQ + 1];    // 1-based; p[0] = current row
    __shared__ int    chosen[NT + 2];
    __shared__ double keyc[NT + 2];
    __shared__ double s_rv[8];
    __shared__ int    s_ri[8];
    __shared__ double s_key;
    __shared__ int    s_j1, s_i0;

    for (int j = tid; j < NQ; j += LTH) { v[j] = 0.0; p[j + 1] = 0; }
    if (tid <= NT) u[tid] = 0.0;
    if (tid == 0) p[0] = 0;
    __syncthreads();

    for (int i = 1; i <= NT; i++) {
        double key[LK];
        #pragma unroll
        for (int k = 0; k < LK; k++) key[k] = DINF;
        unsigned usedm = 0;
        if (tid == 0) p[0] = i;

        int    i0 = i;        // row to scan
        int    j0 = 0;        // 1-based tree column being expanded (0 = root)
        double Dprev = 0.0;   // cumulative delta (= key of last chosen column)
        int    S = 0;         // steps taken this phase

        while (true) {
            const double u0 = u[i0];
            const float* __restrict__ crow = cost + (size_t)(i0 - 1) * NQ;

            double bv = DINF;
            int    bi = 0x7fffffff;
            #pragma unroll
            for (int k = 0; k < LK; k++) {
                const int jm1 = tid + LTH * k;
                if (jm1 < NQ && !((usedm >> k) & 1u)) {
                    const double cand =
                        ((double)__ldg(&crow[jm1]) - u0 - v[jm1]) + Dprev;
                    if (cand < key[k]) { key[k] = cand; way[jm1] = j0; }
                    if (key[k] < bv)   { bv = key[k];  bi = jm1; }
                }
            }
            // warp argmin, lowest-index tie-break
            #pragma unroll
            for (int o = 16; o; o >>= 1) {
                const double ov = __shfl_down_sync(~0u, bv, o);
                const int    oi = __shfl_down_sync(~0u, bi, o);
                if (ov < bv || (ov == bv && oi < bi)) { bv = ov; bi = oi; }
            }
            if (lane == 0) { s_rv[warp] = bv; s_ri[warp] = bi; }
            __syncthreads();
            if (tid == 0) {
                double rb = s_rv[0]; int ri = s_ri[0];
                #pragma unroll
                for (int w = 1; w < 8; w++) {
                    if (s_rv[w] < rb || (s_rv[w] == rb && s_ri[w] < ri)) {
                        rb = s_rv[w]; ri = s_ri[w];
                    }
                }
                s_key = rb; s_j1 = ri; s_i0 = p[ri + 1];
                chosen[S] = ri; keyc[S] = rb;
            }
            __syncthreads();

            const int j1  = s_j1;
            const int ni0 = s_i0;
            Dprev = s_key;
            if (tid == (j1 & (LTH - 1))) usedm |= 1u << (j1 >> 8);
            j0 = j1 + 1;
            S++;
            if (ni0 == 0) break;     // free column found
            i0 = ni0;
        }

        // phase-end dual updates (pre-augment p), log-driven:
        // root: u[i] += Dfinal; step s>=1: col = chosen[s-1], amt = Dfinal - keyc[s-1]
        if (tid == 0) {
            u[i] += Dprev;
        } else if (tid < S) {
            const int    c   = chosen[tid - 1];
            const double amt = Dprev - keyc[tid - 1];
            u[p[c + 1]] += amt;      // rows distinct across used columns
            v[c]        -= amt;
        }
        __syncthreads();

        // augment alternating path
        if (tid == 0) {
            int jj = chosen[S - 1] + 1;
            while (jj) {
                const int jn = way[jj - 1];
                p[jj] = p[jn];
                jj = jn;
            }
        }
        __syncthreads();
    }

    // extract + stable argsort by pred index (indices distinct)
    if (tid == 0) {
        int preds[NT];
        for (int j = 1; j <= NQ; j++)
            if (p[j] > 0) preds[p[j] - 1] = j - 1;

        int order[NT];
        for (int k = 0; k < NT; k++) order[k] = k;
        for (int a = 1; a < NT; a++) {
            const int o = order[a];
            const int keyv = preds[o];
            int c = a - 1;
            while (c >= 0 && preds[order[c]] > keyv) { order[c + 1] = order[c]; c--; }
            order[c + 1] = o;
        }
        for (int k = 0; k < NT; k++) {
            outPred[b * NT + k] = (float)preds[order[k]];
            outTgt[b * NT + k]  = (float)order[k];
        }
    }
}

// ---------------------------------------------------------------------------
extern "C" void kernel_launch(void* const* d_in, const int* in_sizes, int n_in,
                              void* d_out, int out_size)
{
    const float* logits = (const float*)d_in[0];   // (32,900,91) f32
    const float* boxes  = (const float*)d_in[1];   // (32,900,4)  f32
    const int*   labels = (const int*)d_in[2];     // (32,30)     i32
    const float* tboxes = (const float*)d_in[3];   // (32,30,4)   f32

    float* out = (float*)d_out;
    float* outC    = out;                                  // 32*900*960
    float* outPred = out + (size_t)BS * NQ * NTT;          // 960
    float* outTgt  = outPred + BS * NT;                    // 960

    cost_kernel<<<(BS * NQ) / 16, 256>>>(logits, boxes, labels, tboxes, outC);
    lsa_kernel<<<BS, LTH>>>(outPred, outTgt);
}

// round 6
// speedup vs baseline: 3.4171x; 1.3593x over previous
#include <cuda_runtime.h>
#include <cuda_bf16.h>
#include <math.h>

#define BS 32
#define NQ 900
#define NC 91
#define NT 30
#define NTT (BS * NT)   // 960

// slice: g_slice[b][t][q] = C[b, q, b*NT + t]
__device__ float g_slice[BS * NT * NQ];
__device__ int   g_done[BS];

// ---------------------------------------------------------------------------
struct CostSm {
    float4 xy[NTT];          // bx0,by0,bx1,by1
    float4 cw[NTT];          // tx,ty,tw,th
    float  areaB[NTT];
    int    lab[NTT];
    float  sprob[16][NC + 1];  // stores (1 - prob)
};
struct LsaSm {
    double u[NT + 2];
    double keyc[NT + 2];
    int    chosen[NT + 2];
    int    way[NQ];
    int    p[NQ + 1];
    unsigned long long rk[8];
    int    ri[8];
    double skey;
    int    sj1, si0;
};
union SmemU { CostSm c; LsaSm l; };

// cost = 5*l1 + (1-prob) + 2*(2 - inter/uni - uni/encl)
__device__ __forceinline__ float pair_cost(
    float cx, float cy, float w, float h,
    float ax0, float ay0, float ax1, float ay1, float areaA, float cc,
    float tx, float ty, float tw, float th,
    float bx0, float by0, float bx1, float by1, float areaB)
{
    const float l1 = fabsf(cx - tx) + fabsf(cy - ty) + fabsf(w - tw) + fabsf(h - th);
    const float iw = fmaxf(fminf(ax1, bx1) - fmaxf(ax0, bx0), 0.0f);
    const float ih = fmaxf(fminf(ay1, by1) - fmaxf(ay0, by0), 0.0f);
    const float inter = iw * ih;
    const float uni = areaA + areaB - inter;
    const float encl = (fmaxf(ax1, bx1) - fminf(ax0, bx0))
                     * (fmaxf(ay1, by1) - fminf(ay0, by0));
    return 5.0f * l1 + cc + 4.0f
         - 2.0f * __fdividef(inter, uni)
         - 2.0f * __fdividef(uni, encl);
}

__device__ __forceinline__ unsigned long long dmap(double d) {
    long long s = __double_as_longlong(d);
    return (unsigned long long)(s < 0 ? ~s : (s | 0x8000000000000000ll));
}
__device__ __forceinline__ double dunmap(unsigned long long u) {
    long long s = (u & 0x8000000000000000ull)
                ? (long long)(u & 0x7fffffffffffffffull)
                : ~(long long)u;
    return __longlong_as_double(s);
}

// ---------------------------------------------------------------------------
// Slice role: compute g_slice for one batch fast, then raise g_done[b].
// ---------------------------------------------------------------------------
__device__ void slice_role(int b,
    const float* __restrict__ logits, const float* __restrict__ boxes,
    const int* __restrict__ labels, const float* __restrict__ tboxes)
{
    const int tid = threadIdx.x, warp = tid >> 5, lane = tid & 31;

    int lab_t = 0;
    float tx = 0, ty = 0, tw = 0, th = 0, bx0 = 0, by0 = 0, bx1 = 0, by1 = 0, areaB = 0;
    if (lane < NT) {
        lab_t = labels[b * NT + lane];
        const float4 tb = reinterpret_cast<const float4*>(tboxes)[b * NT + lane];
        tx = tb.x; ty = tb.y; tw = tb.z; th = tb.w;
        bx0 = tx - 0.5f * tw; by0 = ty - 0.5f * th;
        bx1 = tx + 0.5f * tw; by1 = ty + 0.5f * th;
        areaB = (bx1 - bx0) * (by1 - by0);
    }

    for (int q0 = warp; q0 < NQ; q0 += 16) {
        #pragma unroll
        for (int r = 0; r < 2; r++) {
            const int q = q0 + 8 * r;
            if (q >= NQ) break;
            const float* lr = logits + ((size_t)b * NQ + q) * NC;
            const float a0 = lr[lane];
            const float a1 = lr[lane + 32];
            const float a2 = (lane < NC - 64) ? lr[lane + 64] : -1e30f;
            float m = fmaxf(fmaxf(a0, a1), a2);
            #pragma unroll
            for (int o = 16; o; o >>= 1) m = fmaxf(m, __shfl_xor_sync(~0u, m, o));
            float s = __expf(a0 - m) + __expf(a1 - m)
                    + ((lane < NC - 64) ? __expf(a2 - m) : 0.0f);
            #pragma unroll
            for (int o = 16; o; o >>= 1) s += __shfl_xor_sync(~0u, s, o);
            if (lane < NT) {
                const float cc = 1.0f - __fdividef(__expf(__ldg(&lr[lab_t]) - m), s);
                const float4 pb = reinterpret_cast<const float4*>(boxes)[b * NQ + q];
                const float ax0 = pb.x - 0.5f * pb.z, ay0 = pb.y - 0.5f * pb.w;
                const float ax1 = pb.x + 0.5f * pb.z, ay1 = pb.y + 0.5f * pb.w;
                const float areaA = (ax1 - ax0) * (ay1 - ay0);
                g_slice[((size_t)(b * NT + lane)) * NQ + q] =
                    pair_cost(pb.x, pb.y, pb.z, pb.w, ax0, ay0, ax1, ay1, areaA, cc,
                              tx, ty, tw, th, bx0, by0, bx1, by1, areaB);
            }
        }
    }
    __syncthreads();
    __threadfence();
    if (tid == 0) atomicExch(&g_done[b], 1);
}

// ---------------------------------------------------------------------------
// LSA role: deferred-dual JV, uint64-ordered keys, v in registers.
// ---------------------------------------------------------------------------
__device__ void lsa_role(SmemU& sm, int b, float* outPred, float* outTgt)
{
    const int tid = threadIdx.x, warp = tid >> 5, lane = tid & 31;

    if (tid == 0) { while (atomicAdd(&g_done[b], 0) == 0) __nanosleep(128); }
    __syncthreads();
    __threadfence();

    const float* __restrict__ cost = g_slice + (size_t)b * NT * NQ;
    const unsigned long long KINF = 0xffffffffffffffffull;
    const bool act = (tid * 4 < NQ);   // tid < 225

    for (int j = tid; j < NQ; j += 256) sm.l.p[j + 1] = 0;
    if (tid <= NT) sm.l.u[tid] = 0.0;
    double v[4] = {0.0, 0.0, 0.0, 0.0};
    __syncthreads();

    for (int i = 1; i <= NT; i++) {
        unsigned long long key[4] = {KINF, KINF, KINF, KINF};
        int usedm = 0;
        int i0 = i, j0 = 0, S = 0;
        double Dprev = 0.0;

        while (true) {
            const double u0 = sm.l.u[i0];
            const float* __restrict__ crow = cost + (size_t)(i0 - 1) * NQ;

            unsigned long long bk = KINF;
            int bi = 0x7fffffff;
            if (act) {
                const float4 c4 = *reinterpret_cast<const float4*>(crow + 4 * tid);
                const float cv[4] = {c4.x, c4.y, c4.z, c4.w};
                #pragma unroll
                for (int k = 0; k < 4; k++) {
                    if (!((usedm >> k) & 1)) {
                        const double cand = ((double)cv[k] - u0 - v[k]) + Dprev;
                        const unsigned long long ku = dmap(cand);
                        if (ku < key[k]) { key[k] = ku; sm.l.way[4 * tid + k] = j0; }
                        if (key[k] < bk) { bk = key[k]; bi = 4 * tid + k; }
                    }
                }
            }
            #pragma unroll
            for (int o = 16; o; o >>= 1) {
                const unsigned long long ok_ = __shfl_down_sync(~0u, bk, o);
                const int oi = __shfl_down_sync(~0u, bi, o);
                if (ok_ < bk || (ok_ == bk && oi < bi)) { bk = ok_; bi = oi; }
            }
            if (lane == 0) { sm.l.rk[warp] = bk; sm.l.ri[warp] = bi; }
            __syncthreads();
            if (tid == 0) {
                unsigned long long rb = sm.l.rk[0]; int rbi = sm.l.ri[0];
                #pragma unroll
                for (int w = 1; w < 8; w++) {
                    const unsigned long long wk = sm.l.rk[w]; const int wi = sm.l.ri[w];
                    if (wk < rb || (wk == rb && wi < rbi)) { rb = wk; rbi = wi; }
                }
                const double d = dunmap(rb);
                sm.l.skey = d; sm.l.sj1 = rbi; sm.l.si0 = sm.l.p[rbi + 1];
                sm.l.chosen[S] = rbi; sm.l.keyc[S] = d;
            }
            __syncthreads();
            const int j1 = sm.l.sj1, ni0 = sm.l.si0;
            Dprev = sm.l.skey;
            if (act && (j1 >> 2) == tid) usedm |= 1 << (j1 & 3);
            j0 = j1 + 1;
            S++;
            if (ni0 == 0) break;
            i0 = ni0;
        }

        // phase-end dual updates (before augment): root + used columns
        if (tid == 0) {
            sm.l.u[i] += Dprev;
        } else if (tid < S) {
            const int c = sm.l.chosen[tid - 1];
            sm.l.u[sm.l.p[c + 1]] += Dprev - sm.l.keyc[tid - 1];
        }
        if (act) {
            for (int s = 0; s < S - 1; s++) {
                const int c = sm.l.chosen[s];
                if ((c >> 2) == tid) v[c & 3] -= Dprev - sm.l.keyc[s];
            }
        }
        __syncthreads();

        // augment: predecessor 0 is the virtual root column holding row i
        if (tid == 0) {
            int jj = sm.l.chosen[S - 1] + 1;
            while (jj) {
                const int jn = sm.l.way[jj - 1];
                sm.l.p[jj] = jn ? sm.l.p[jn] : i;
                jj = jn;
            }
        }
        __syncthreads();
    }

    if (tid == 0) {
        int preds[NT];
        for (int j = 1; j <= NQ; j++)
            if (sm.l.p[j] > 0) preds[sm.l.p[j] - 1] = j - 1;
        int order[NT];
        for (int k = 0; k < NT; k++) order[k] = k;
        for (int a = 1; a < NT; a++) {
            const int o = order[a];
            const int kv = preds[o];
            int c = a - 1;
            while (c >= 0 && preds[order[c]] > kv) { order[c + 1] = order[c]; c--; }
            order[c + 1] = o;
        }
        for (int k = 0; k < NT; k++) {
            outPred[b * NT + k] = (float)preds[order[k]];
            outTgt[b * NT + k]  = (float)order[k];
        }
    }
}

// ---------------------------------------------------------------------------
// Cost role: 16 rows per block, 2 rows/warp, streams all 960 columns.
// ---------------------------------------------------------------------------
__device__ void cost_role(SmemU& sm, int cb,
    const float* __restrict__ logits, const float* __restrict__ boxes,
    const int* __restrict__ labels, const float* __restrict__ tboxes,
    float* __restrict__ C)
{
    const int tid = threadIdx.x, warp = tid >> 5, lane = tid & 31;

    for (int j = tid; j < NTT; j += 256) {
        const float4 tb = reinterpret_cast<const float4*>(tboxes)[j];
        const float bx0 = tb.x - 0.5f * tb.z, by0 = tb.y - 0.5f * tb.w;
        const float bx1 = tb.x + 0.5f * tb.z, by1 = tb.y + 0.5f * tb.w;
        sm.c.cw[j] = tb;
        sm.c.xy[j] = make_float4(bx0, by0, bx1, by1);
        sm.c.areaB[j] = (bx1 - bx0) * (by1 - by0);
        sm.c.lab[j] = labels[j];
    }
    __syncthreads();

    const int rbase = cb * 16 + warp * 2;

    #pragma unroll
    for (int rr = 0; rr < 2; rr++) {
        const int row = rbase + rr;
        const float* lr = logits + (size_t)row * NC;
        const float a0 = lr[lane];
        const float a1 = lr[lane + 32];
        const float a2 = (lane < NC - 64) ? lr[lane + 64] : -1e30f;
        float m = fmaxf(fmaxf(a0, a1), a2);
        #pragma unroll
        for (int o = 16; o; o >>= 1) m = fmaxf(m, __shfl_xor_sync(~0u, m, o));
        const float e0 = __expf(a0 - m);
        const float e1 = __expf(a1 - m);
        const float e2 = (lane < NC - 64) ? __expf(a2 - m) : 0.0f;
        float s = e0 + e1 + e2;
        #pragma unroll
        for (int o = 16; o; o >>= 1) s += __shfl_xor_sync(~0u, s, o);
        const float inv = __fdividef(1.0f, s);
        sm.c.sprob[warp * 2 + rr][lane]      = 1.0f - e0 * inv;
        sm.c.sprob[warp * 2 + rr][lane + 32] = 1.0f - e1 * inv;
        if (lane < NC - 64) sm.c.sprob[warp * 2 + rr][lane + 64] = 1.0f - e2 * inv;
    }
    __syncwarp();

    const float4 p0 = reinterpret_cast<const float4*>(boxes)[rbase];
    const float4 p1 = reinterpret_cast<const float4*>(boxes)[rbase + 1];
    const float ax00 = p0.x - 0.5f * p0.z, ay00 = p0.y - 0.5f * p0.w;
    const float ax01 = p0.x + 0.5f * p0.z, ay01 = p0.y + 0.5f * p0.w;
    const float arA0 = (ax01 - ax00) * (ay01 - ay00);
    const float ax10 = p1.x - 0.5f * p1.z, ay10 = p1.y - 0.5f * p1.w;
    const float ax11 = p1.x + 0.5f * p1.z, ay11 = p1.y + 0.5f * p1.w;
    const float arA1 = (ax11 - ax10) * (ay11 - ay10);

    const float* pr0 = sm.c.sprob[warp * 2];
    const float* pr1 = sm.c.sprob[warp * 2 + 1];
    float* __restrict__ c0 = C + (size_t)rbase * NTT;
    float* __restrict__ c1 = c0 + NTT;

    #pragma unroll 5
    for (int k = 0; k < 30; k++) {
        const int j = lane + 32 * k;
        const float4 X = sm.c.xy[j];
        const float4 W = sm.c.cw[j];
        const float ab = sm.c.areaB[j];
        const int lb = sm.c.lab[j];
        c0[j] = pair_cost(p0.x, p0.y, p0.z, p0.w, ax00, ay00, ax01, ay01, arA0, pr0[lb],
                          W.x, W.y, W.z, W.w, X.x, X.y, X.z, X.w, ab);
        c1[j] = pair_cost(p1.x, p1.y, p1.z, p1.w, ax10, ay10, ax11, ay11, arA1, pr1[lb],
                          W.x, W.y, W.z, W.w, X.x, X.y, X.z, X.w, ab);
    }
}

// ---------------------------------------------------------------------------
__global__ void reset_kernel() {
    if (threadIdx.x < BS) g_done[threadIdx.x] = 0;
}

__global__ __launch_bounds__(256) void fused_kernel(
    const float* __restrict__ logits, const float* __restrict__ boxes,
    const int* __restrict__ labels, const float* __restrict__ tboxes,
    float* __restrict__ C, float* __restrict__ outPred, float* __restrict__ outTgt)
{
    __shared__ SmemU sm;
    const int bid = blockIdx.x;
    if (bid < BS) {
        slice_role(bid, logits, boxes, labels, tboxes);
    } else if (bid < 2 * BS) {
        lsa_role(sm, bid - BS, outPred, outTgt);
    } else {
        cost_role(sm, bid - 2 * BS, logits, boxes, labels, tboxes, C);
    }
}

// ---------------------------------------------------------------------------
extern "C" void kernel_launch(void* const* d_in, const int* in_sizes, int n_in,
                              void* d_out, int out_size)
{
    const float* logits = (const float*)d_in[0];   // (32,900,91) f32
    const float* boxes  = (const float*)d_in[1];   // (32,900,4)  f32
    const int*   labels = (const int*)d_in[2];     // (32,30)     i32
    const float* tboxes = (const float*)d_in[3];   // (32,30,4)   f32

    float* out = (float*)d_out;
    float* outC    = out;                                  // 32*900*960
    float* outPred = out + (size_t)BS * NQ * NTT;          // 960
    float* outTgt  = outPred + BS * NT;                    // 960

    reset_kernel<<<1, 32>>>();
    fused_kernel<<<2 * BS + (BS * NQ) / 16, 256>>>(
        logits, boxes, labels, tboxes, outC, outPred, outTgt);
}

// round 7
// speedup vs baseline: 3.5942x; 1.0518x over previous
#include <cuda_runtime.h>
#include <cuda_bf16.h>
#include <math.h>

#define BS 32
#define NQ 900
#define NC 91
#define NT 30
#define NTT (BS * NT)   // 960

// slice: g_slice[b][t][q] = C[b, q, b*NT + t]
__device__ float g_slice[BS * NT * NQ];
__device__ int   g_done[BS];

// ---------------------------------------------------------------------------
struct CostSm {
    float4 xy[NTT];          // bx0,by0,bx1,by1
    float4 cw[NTT];          // tx,ty,tw,th
    float  areaB[NTT];
    int    lab[NTT];
    float  sprob[16][NC + 1];  // (1 - prob)
};
struct LsaSm {
    float  cost[NT][NQ];     // 105.5 KB: the batch's cost slice
    double u[NT + 2];
    double keyc[NT + 2];
    unsigned long long rk[2][8];
    int    ri[2][8];
    int    chosen[NT + 2];
    int    p[NQ + 1];
    unsigned short way[NQ];
};
union SmemU { CostSm c; LsaSm l; };

// cost = 5*l1 + (1-prob) + 2*(2 - inter/uni - uni/encl)
__device__ __forceinline__ float pair_cost(
    float cx, float cy, float w, float h,
    float ax0, float ay0, float ax1, float ay1, float areaA, float cc,
    float tx, float ty, float tw, float th,
    float bx0, float by0, float bx1, float by1, float areaB)
{
    const float l1 = fabsf(cx - tx) + fabsf(cy - ty) + fabsf(w - tw) + fabsf(h - th);
    const float iw = fmaxf(fminf(ax1, bx1) - fmaxf(ax0, bx0), 0.0f);
    const float ih = fmaxf(fminf(ay1, by1) - fmaxf(ay0, by0), 0.0f);
    const float inter = iw * ih;
    const float uni = areaA + areaB - inter;
    const float encl = (fmaxf(ax1, bx1) - fminf(ax0, bx0))
                     * (fmaxf(ay1, by1) - fminf(ay0, by0));
    return 5.0f * l1 + cc + 4.0f
         - 2.0f * __fdividef(inter, uni)
         - 2.0f * __fdividef(uni, encl);
}

__device__ __forceinline__ unsigned long long dmap(double d) {
    long long s = __double_as_longlong(d);
    return (unsigned long long)(s < 0 ? ~s : (s | 0x8000000000000000ll));
}
__device__ __forceinline__ double dunmap(unsigned long long u) {
    long long s = (u & 0x8000000000000000ull)
                ? (long long)(u & 0x7fffffffffffffffull)
                : ~(long long)u;
    return __longlong_as_double(s);
}

// ---------------------------------------------------------------------------
// Slice role: compute g_slice for one batch fast, then raise g_done[b].
// ---------------------------------------------------------------------------
__device__ void slice_role(int b,
    const float* __restrict__ logits, const float* __restrict__ boxes,
    const int* __restrict__ labels, const float* __restrict__ tboxes)
{
    const int tid = threadIdx.x, warp = tid >> 5, lane = tid & 31;

    int lab_t = 0;
    float tx = 0, ty = 0, tw = 0, th = 0, bx0 = 0, by0 = 0, bx1 = 0, by1 = 0, areaB = 0;
    if (lane < NT) {
        lab_t = labels[b * NT + lane];
        const float4 tb = reinterpret_cast<const float4*>(tboxes)[b * NT + lane];
        tx = tb.x; ty = tb.y; tw = tb.z; th = tb.w;
        bx0 = tx - 0.5f * tw; by0 = ty - 0.5f * th;
        bx1 = tx + 0.5f * tw; by1 = ty + 0.5f * th;
        areaB = (bx1 - bx0) * (by1 - by0);
    }

    for (int q0 = warp; q0 < NQ; q0 += 16) {
        #pragma unroll
        for (int r = 0; r < 2; r++) {
            const int q = q0 + 8 * r;
            if (q >= NQ) break;
            const float* lr = logits + ((size_t)b * NQ + q) * NC;
            const float a0 = lr[lane];
            const float a1 = lr[lane + 32];
            const float a2 = (lane < NC - 64) ? lr[lane + 64] : -1e30f;
            float m = fmaxf(fmaxf(a0, a1), a2);
            #pragma unroll
            for (int o = 16; o; o >>= 1) m = fmaxf(m, __shfl_xor_sync(~0u, m, o));
            float s = __expf(a0 - m) + __expf(a1 - m)
                    + ((lane < NC - 64) ? __expf(a2 - m) : 0.0f);
            #pragma unroll
            for (int o = 16; o; o >>= 1) s += __shfl_xor_sync(~0u, s, o);
            if (lane < NT) {
                const float cc = 1.0f - __fdividef(__expf(__ldg(&lr[lab_t]) - m), s);
                const float4 pb = reinterpret_cast<const float4*>(boxes)[b * NQ + q];
                const float ax0 = pb.x - 0.5f * pb.z, ay0 = pb.y - 0.5f * pb.w;
                const float ax1 = pb.x + 0.5f * pb.z, ay1 = pb.y + 0.5f * pb.w;
                const float areaA = (ax1 - ax0) * (ay1 - ay0);
                g_slice[((size_t)(b * NT + lane)) * NQ + q] =
                    pair_cost(pb.x, pb.y, pb.z, pb.w, ax0, ay0, ax1, ay1, areaA, cc,
                              tx, ty, tw, th, bx0, by0, bx1, by1, areaB);
            }
        }
    }
    __syncthreads();
    __threadfence();
    if (tid == 0) atomicExch(&g_done[b], 1);
}

// ---------------------------------------------------------------------------
// LSA role: deferred-dual JV, smem-resident cost rows, 1 barrier per step.
// ---------------------------------------------------------------------------
__device__ void lsa_role(SmemU& sm, int b, float* outPred, float* outTgt)
{
    const int tid = threadIdx.x, warp = tid >> 5, lane = tid & 31;

    if (tid == 0) { while (atomicAdd(&g_done[b], 0) == 0) __nanosleep(128); }
    __syncthreads();
    __threadfence();

    const unsigned long long KINF = 0xffffffffffffffffull;
    const bool act = (tid * 4 < NQ);   // tid < 225

    // copy cost slice to shared (L2 -> SMEM)
    {
        const float4* src = reinterpret_cast<const float4*>(g_slice + (size_t)b * NT * NQ);
        float4* dst = reinterpret_cast<float4*>(&sm.l.cost[0][0]);
        for (int idx = tid; idx < NT * NQ / 4; idx += 256) dst[idx] = src[idx];
    }
    for (int j = tid; j < NQ; j += 256) sm.l.p[j + 1] = 0;
    if (tid <= NT) sm.l.u[tid] = 0.0;
    double v[4] = {0.0, 0.0, 0.0, 0.0};
    int par = 0;
    __syncthreads();

    for (int i = 1; i <= NT; i++) {
        unsigned long long key[4] = {KINF, KINF, KINF, KINF};
        int usedm = 0;
        int i0 = i, j0 = 0, S = 0;
        double Dprev = 0.0;

        while (true) {
            const double u0 = sm.l.u[i0];
            const float* __restrict__ crow = sm.l.cost[i0 - 1];

            unsigned long long bk = KINF;
            int bi = 0x7fffffff;
            if (act) {
                const float4 c4 = *reinterpret_cast<const float4*>(crow + 4 * tid);
                const float cv[4] = {c4.x, c4.y, c4.z, c4.w};
                #pragma unroll
                for (int k = 0; k < 4; k++) {
                    if (!((usedm >> k) & 1)) {
                        const double cand = ((double)cv[k] - u0 - v[k]) + Dprev;
                        const unsigned long long ku = dmap(cand);
                        if (ku < key[k]) {
                            key[k] = ku;
                            sm.l.way[4 * tid + k] = (unsigned short)j0;
                        }
                        if (key[k] < bk) { bk = key[k]; bi = 4 * tid + k; }
                    }
                }
            }
            // warp argmin (lowest-index tie-break)
            #pragma unroll
            for (int o = 16; o; o >>= 1) {
                const unsigned long long ok_ = __shfl_down_sync(~0u, bk, o);
                const int oi = __shfl_down_sync(~0u, bi, o);
                if (ok_ < bk || (ok_ == bk && oi < bi)) { bk = ok_; bi = oi; }
            }
            if (lane == 0) { sm.l.rk[par][warp] = bk; sm.l.ri[par][warp] = bi; }
            __syncthreads();                       // the ONLY barrier per step

            // every warp merges the 8 partials (identical result everywhere)
            unsigned long long mk = (lane < 8) ? sm.l.rk[par][lane] : KINF;
            int mi = (lane < 8) ? sm.l.ri[par][lane] : 0x7fffffff;
            #pragma unroll
            for (int o = 4; o; o >>= 1) {
                const unsigned long long ok_ = __shfl_down_sync(~0u, mk, o);
                const int oi = __shfl_down_sync(~0u, mi, o);
                if (ok_ < mk || (ok_ == mk && oi < mi)) { mk = ok_; mi = oi; }
            }
            mk = __shfl_sync(~0u, mk, 0);
            mi = __shfl_sync(~0u, mi, 0);

            const int j1 = mi;
            Dprev = dunmap(mk);
            if (tid == 0) { sm.l.chosen[S] = j1; sm.l.keyc[S] = Dprev; }
            const int ni0 = sm.l.p[j1 + 1];        // broadcast smem read
            if (act && (j1 >> 2) == tid) usedm |= 1 << (j1 & 3);
            j0 = j1 + 1;
            S++;
            par ^= 1;
            if (ni0 == 0) break;
            i0 = ni0;
        }
        __syncthreads();   // chosen/keyc/way visible; scans finished

        // phase-end dual updates (before augment)
        if (tid == 0) {
            sm.l.u[i] += Dprev;
        } else if (tid < S) {
            const int c = sm.l.chosen[tid - 1];
            sm.l.u[sm.l.p[c + 1]] += Dprev - sm.l.keyc[tid - 1];
        }
        if (act) {
            for (int s = 0; s < S - 1; s++) {
                const int c = sm.l.chosen[s];
                if ((c >> 2) == tid) v[c & 3] -= Dprev - sm.l.keyc[s];
            }
        }
        __syncthreads();

        // augment: predecessor 0 is the virtual root column holding row i
        if (tid == 0) {
            int jj = sm.l.chosen[S - 1] + 1;
            while (jj) {
                const int jn = (int)sm.l.way[jj - 1];
                sm.l.p[jj] = jn ? sm.l.p[jn] : i;
                jj = jn;
            }
        }
        __syncthreads();
    }

    if (tid == 0) {
        int preds[NT];
        for (int j = 1; j <= NQ; j++)
            if (sm.l.p[j] > 0) preds[sm.l.p[j] - 1] = j - 1;
        int order[NT];
        for (int k = 0; k < NT; k++) order[k] = k;
        for (int a = 1; a < NT; a++) {
            const int o = order[a];
            const int kv = preds[o];
            int c = a - 1;
            while (c >= 0 && preds[order[c]] > kv) { order[c + 1] = order[c]; c--; }
            order[c + 1] = o;
        }
        for (int k = 0; k < NT; k++) {
            outPred[b * NT + k] = (float)preds[order[k]];
            outTgt[b * NT + k]  = (float)order[k];
        }
    }
}

// ---------------------------------------------------------------------------
// Cost role: 16 rows per block, 2 rows/warp, streams all 960 columns.
// ---------------------------------------------------------------------------
__device__ void cost_role(SmemU& sm, int cb,
    const float* __restrict__ logits, const float* __restrict__ boxes,
    const int* __restrict__ labels, const float* __restrict__ tboxes,
    float* __restrict__ C)
{
    const int tid = threadIdx.x, warp = tid >> 5, lane = tid & 31;

    for (int j = tid; j < NTT; j += 256) {
        const float4 tb = reinterpret_cast<const float4*>(tboxes)[j];
        const float bx0 = tb.x - 0.5f * tb.z, by0 = tb.y - 0.5f * tb.w;
        const float bx1 = tb.x + 0.5f * tb.z, by1 = tb.y + 0.5f * tb.w;
        sm.c.cw[j] = tb;
        sm.c.xy[j] = make_float4(bx0, by0, bx1, by1);
        sm.c.areaB[j] = (bx1 - bx0) * (by1 - by0);
        sm.c.lab[j] = labels[j];
    }
    __syncthreads();

    const int rbase = cb * 16 + warp * 2;

    #pragma unroll
    for (int rr = 0; rr < 2; rr++) {
        const int row = rbase + rr;
        const float* lr = logits + (size_t)row * NC;
        const float a0 = lr[lane];
        const float a1 = lr[lane + 32];
        const float a2 = (lane < NC - 64) ? lr[lane + 64] : -1e30f;
        float m = fmaxf(fmaxf(a0, a1), a2);
        #pragma unroll
        for (int o = 16; o; o >>= 1) m = fmaxf(m, __shfl_xor_sync(~0u, m, o));
        const float e0 = __expf(a0 - m);
        const float e1 = __expf(a1 - m);
        const float e2 = (lane < NC - 64) ? __expf(a2 - m) : 0.0f;
        float s = e0 + e1 + e2;
        #pragma unroll
        for (int o = 16; o; o >>= 1) s += __shfl_xor_sync(~0u, s, o);
        const float inv = __fdividef(1.0f, s);
        sm.c.sprob[warp * 2 + rr][lane]      = 1.0f - e0 * inv;
        sm.c.sprob[warp * 2 + rr][lane + 32] = 1.0f - e1 * inv;
        if (lane < NC - 64) sm.c.sprob[warp * 2 + rr][lane + 64] = 1.0f - e2 * inv;
    }
    __syncwarp();

    const float4 p0 = reinterpret_cast<const float4*>(boxes)[rbase];
    const float4 p1 = reinterpret_cast<const float4*>(boxes)[rbase + 1];
    const float ax00 = p0.x - 0.5f * p0.z, ay00 = p0.y - 0.5f * p0.w;
    const float ax01 = p0.x + 0.5f * p0.z, ay01 = p0.y + 0.5f * p0.w;
    const float arA0 = (ax01 - ax00) * (ay01 - ay00);
    const float ax10 = p1.x - 0.5f * p1.z, ay10 = p1.y - 0.5f * p1.w;
    const float ax11 = p1.x + 0.5f * p1.z, ay11 = p1.y + 0.5f * p1.w;
    const float arA1 = (ax11 - ax10) * (ay11 - ay10);

    const float* pr0 = sm.c.sprob[warp * 2];
    const float* pr1 = sm.c.sprob[warp * 2 + 1];
    float* __restrict__ c0 = C + (size_t)rbase * NTT;
    float* __restrict__ c1 = c0 + NTT;

    #pragma unroll 5
    for (int k = 0; k < 30; k++) {
        const int j = lane + 32 * k;
        const float4 X = sm.c.xy[j];
        const float4 W = sm.c.cw[j];
        const float ab = sm.c.areaB[j];
        const int lb = sm.c.lab[j];
        c0[j] = pair_cost(p0.x, p0.y, p0.z, p0.w, ax00, ay00, ax01, ay01, arA0, pr0[lb],
                          W.x, W.y, W.z, W.w, X.x, X.y, X.z, X.w, ab);
        c1[j] = pair_cost(p1.x, p1.y, p1.z, p1.w, ax10, ay10, ax11, ay11, arA1, pr1[lb],
                          W.x, W.y, W.z, W.w, X.x, X.y, X.z, X.w, ab);
    }
}

// ---------------------------------------------------------------------------
__global__ void reset_kernel() {
    if (threadIdx.x < BS) g_done[threadIdx.x] = 0;
}

__global__ __launch_bounds__(256) void fused_kernel(
    const float* __restrict__ logits, const float* __restrict__ boxes,
    const int* __restrict__ labels, const float* __restrict__ tboxes,
    float* __restrict__ C, float* __restrict__ outPred, float* __restrict__ outTgt)
{
    extern __shared__ __align__(16) unsigned char dynsm[];
    SmemU& sm = *reinterpret_cast<SmemU*>(dynsm);

    const int bid = blockIdx.x;
    if (bid < BS) {
        slice_role(bid, logits, boxes, labels, tboxes);
    } else if (bid < 2 * BS) {
        lsa_role(sm, bid - BS, outPred, outTgt);
    } else {
        cost_role(sm, bid - 2 * BS, logits, boxes, labels, tboxes, C);
    }
}

// ---------------------------------------------------------------------------
extern "C" void kernel_launch(void* const* d_in, const int* in_sizes, int n_in,
                              void* d_out, int out_size)
{
    const float* logits = (const float*)d_in[0];   // (32,900,91) f32
    const float* boxes  = (const float*)d_in[1];   // (32,900,4)  f32
    const int*   labels = (const int*)d_in[2];     // (32,30)     i32
    const float* tboxes = (const float*)d_in[3];   // (32,30,4)   f32

    float* out = (float*)d_out;
    float* outC    = out;                                  // 32*900*960
    float* outPred = out + (size_t)BS * NQ * NTT;          // 960
    float* outTgt  = outPred + BS * NT;                    // 960

    cudaFuncSetAttribute(fused_kernel,
                         cudaFuncAttributeMaxDynamicSharedMemorySize,
                         (int)sizeof(SmemU));

    reset_kernel<<<1, 32>>>();
    fused_kernel<<<2 * BS + (BS * NQ) / 16, 256, sizeof(SmemU)>>>(
        logits, boxes, labels, tboxes, outC, outPred, outTgt);
}

// round 9
// speedup vs baseline: 4.8354x; 1.3454x over previous
#include <cuda_runtime.h>
#include <cuda_bf16.h>
#include <math.h>

#define BS 32
#define NQ 900
#define NC 91
#define NT 30
#define NTT (BS * NT)   // 960
#define NTH 512          // threads per block (16 warps)

// slice: g_slice[b][t][q] = C[b, q, b*NT + t]
__device__ float g_slice[BS * NT * NQ];
__device__ int   g_done[BS];

// ---------------------------------------------------------------------------
struct CostSm {
    float4 xy[NTT];            // bx0,by0,bx1,by1
    float4 cw[NTT];            // tx,ty,tw,th
    float  areaB[NTT];
    int    lab[NTT];
    float  sprob[32][NC + 1];  // (1 - prob)
};
struct LsaSm {
    float  cost[NT][NQ];       // 105.5 KB
    double u[NT + 2];
    double keyc[NT + 2];
    unsigned long long rk[2][16];
    int    ri[2][16];
    int    chosen[NT + 2];
    int    p[NQ + 1];
    unsigned short way[NQ];
};
union SmemU { CostSm c; LsaSm l; };

// cost = 5*l1 + (1-prob) + 2*(2 - inter/uni - uni/encl)
__device__ __forceinline__ float pair_cost(
    float cx, float cy, float w, float h,
    float ax0, float ay0, float ax1, float ay1, float areaA, float cc,
    float tx, float ty, float tw, float th,
    float bx0, float by0, float bx1, float by1, float areaB)
{
    const float l1 = fabsf(cx - tx) + fabsf(cy - ty) + fabsf(w - tw) + fabsf(h - th);
    const float iw = fmaxf(fminf(ax1, bx1) - fmaxf(ax0, bx0), 0.0f);
    const float ih = fmaxf(fminf(ay1, by1) - fmaxf(ay0, by0), 0.0f);
    const float inter = iw * ih;
    const float uni = areaA + areaB - inter;
    const float encl = (fmaxf(ax1, bx1) - fminf(ax0, bx0))
                     * (fmaxf(ay1, by1) - fminf(ay0, by0));
    return 5.0f * l1 + cc + 4.0f
         - 2.0f * __fdividef(inter, uni)
         - 2.0f * __fdividef(uni, encl);
}

__device__ __forceinline__ unsigned long long dmap(double d) {
    long long s = __double_as_longlong(d);
    return (unsigned long long)(s < 0 ? ~s : (s | 0x8000000000000000ll));
}
__device__ __forceinline__ double dunmap(unsigned long long u) {
    long long s = (u & 0x8000000000000000ull)
                ? (long long)(u & 0x7fffffffffffffffull)
                : ~(long long)u;
    return __longlong_as_double(s);
}

// ---------------------------------------------------------------------------
// Slice role: compute g_slice for one batch fast, then raise g_done[b].
// ---------------------------------------------------------------------------
__device__ void slice_role(int b,
    const float* __restrict__ logits, const float* __restrict__ boxes,
    const int* __restrict__ labels, const float* __restrict__ tboxes)
{
    const int tid = threadIdx.x, warp = tid >> 5, lane = tid & 31;

    int lab_t = 0;
    float tx = 0, ty = 0, tw = 0, th = 0, bx0 = 0, by0 = 0, bx1 = 0, by1 = 0, areaB = 0;
    if (lane < NT) {
        lab_t = labels[b * NT + lane];
        const float4 tb = reinterpret_cast<const float4*>(tboxes)[b * NT + lane];
        tx = tb.x; ty = tb.y; tw = tb.z; th = tb.w;
        bx0 = tx - 0.5f * tw; by0 = ty - 0.5f * th;
        bx1 = tx + 0.5f * tw; by1 = ty + 0.5f * th;
        areaB = (bx1 - bx0) * (by1 - by0);
    }

    for (int q = warp; q < NQ; q += 16) {
        const float* lr = logits + ((size_t)b * NQ + q) * NC;
        const float a0 = lr[lane];
        const float a1 = lr[lane + 32];
        const float a2 = (lane < NC - 64) ? lr[lane + 64] : -1e30f;
        float m = fmaxf(fmaxf(a0, a1), a2);
        #pragma unroll
        for (int o = 16; o; o >>= 1) m = fmaxf(m, __shfl_xor_sync(~0u, m, o));
        float s = __expf(a0 - m) + __expf(a1 - m)
                + ((lane < NC - 64) ? __expf(a2 - m) : 0.0f);
        #pragma unroll
        for (int o = 16; o; o >>= 1) s += __shfl_xor_sync(~0u, s, o);
        if (lane < NT) {
            const float cc = 1.0f - __fdividef(__expf(__ldg(&lr[lab_t]) - m), s);
            const float4 pb = reinterpret_cast<const float4*>(boxes)[b * NQ + q];
            const float ax0 = pb.x - 0.5f * pb.z, ay0 = pb.y - 0.5f * pb.w;
            const float ax1 = pb.x + 0.5f * pb.z, ay1 = pb.y + 0.5f * pb.w;
            const float areaA = (ax1 - ax0) * (ay1 - ay0);
            g_slice[((size_t)(b * NT + lane)) * NQ + q] =
                pair_cost(pb.x, pb.y, pb.z, pb.w, ax0, ay0, ax1, ay1, areaA, cc,
                          tx, ty, tw, th, bx0, by0, bx1, by1, areaB);
        }
    }
    __syncthreads();
    __threadfence();
    if (tid == 0) atomicExch(&g_done[b], 1);
}

// ---------------------------------------------------------------------------
// LSA role: deferred-dual JV, smem-resident cost rows, 1 barrier per step.
// 512 threads, 2 columns per thread (tid < 450 active).
// ---------------------------------------------------------------------------
__device__ void lsa_role(SmemU& sm, int b, float* outPred, float* outTgt)
{
    const int tid = threadIdx.x, warp = tid >> 5, lane = tid & 31;

    if (tid == 0) { while (atomicAdd(&g_done[b], 0) == 0) __nanosleep(128); }
    __syncthreads();
    __threadfence();

    const unsigned long long KINF = 0xffffffffffffffffull;
    const bool act = (tid * 2 < NQ);   // tid < 450

    // copy cost slice to shared
    {
        const float4* src = reinterpret_cast<const float4*>(g_slice + (size_t)b * NT * NQ);
        float4* dst = reinterpret_cast<float4*>(&sm.l.cost[0][0]);
        for (int idx = tid; idx < NT * NQ / 4; idx += NTH) dst[idx] = src[idx];
    }
    for (int j = tid; j < NQ; j += NTH) sm.l.p[j + 1] = 0;
    if (tid <= NT) sm.l.u[tid] = 0.0;
    double v[2] = {0.0, 0.0};
    int par = 0;
    __syncthreads();

    for (int i = 1; i <= NT; i++) {
        unsigned long long key[2] = {KINF, KINF};
        int usedm = 0;
        int i0 = i, j0 = 0, S = 0;
        double Dprev = 0.0;

        while (true) {
            const double u0 = sm.l.u[i0];
            const float* __restrict__ crow = sm.l.cost[i0 - 1];

            unsigned long long bk = KINF;
            int bi = 0x7fffffff;
            if (act) {
                const float2 c2 = *reinterpret_cast<const float2*>(crow + 2 * tid);
                const float cv[2] = {c2.x, c2.y};
                #pragma unroll
                for (int k = 0; k < 2; k++) {
                    if (!((usedm >> k) & 1)) {
                        const double cand = ((double)cv[k] - u0 - v[k]) + Dprev;
                        const unsigned long long ku = dmap(cand);
                        if (ku < key[k]) {
                            key[k] = ku;
                            sm.l.way[2 * tid + k] = (unsigned short)j0;
                        }
                        if (key[k] < bk) { bk = key[k]; bi = 2 * tid + k; }
                    }
                }
            }
            // warp argmin (lowest-index tie-break)
            #pragma unroll
            for (int o = 16; o; o >>= 1) {
                const unsigned long long ok_ = __shfl_down_sync(~0u, bk, o);
                const int oi = __shfl_down_sync(~0u, bi, o);
                if (ok_ < bk || (ok_ == bk && oi < bi)) { bk = ok_; bi = oi; }
            }
            if (lane == 0) { sm.l.rk[par][warp] = bk; sm.l.ri[par][warp] = bi; }
            __syncthreads();                       // the ONLY barrier per step

            // every warp merges the 16 partials (identical result everywhere)
            unsigned long long mk = (lane < 16) ? sm.l.rk[par][lane] : KINF;
            int mi = (lane < 16) ? sm.l.ri[par][lane] : 0x7fffffff;
            #pragma unroll
            for (int o = 8; o; o >>= 1) {
                const unsigned long long ok_ = __shfl_down_sync(~0u, mk, o);
                const int oi = __shfl_down_sync(~0u, mi, o);
                if (ok_ < mk || (ok_ == mk && oi < mi)) { mk = ok_; mi = oi; }
            }
            mk = __shfl_sync(~0u, mk, 0);
            mi = __shfl_sync(~0u, mi, 0);

            const int j1 = mi;
            Dprev = dunmap(mk);
            if (tid == 0) { sm.l.chosen[S] = j1; sm.l.keyc[S] = Dprev; }
            const int ni0 = sm.l.p[j1 + 1];        // broadcast smem read
            if (act && (j1 >> 1) == tid) usedm |= 1 << (j1 & 1);
            j0 = j1 + 1;
            S++;
            par ^= 1;
            if (ni0 == 0) break;
            i0 = ni0;
        }
        __syncthreads();   // chosen/keyc/way visible; scans finished

        // phase-end dual updates (before augment)
        if (tid == 0) {
            sm.l.u[i] += Dprev;
        } else if (tid < S) {
            const int c = sm.l.chosen[tid - 1];
            sm.l.u[sm.l.p[c + 1]] += Dprev - sm.l.keyc[tid - 1];
        }
        if (act) {
            for (int s = 0; s < S - 1; s++) {
                const int c = sm.l.chosen[s];
                if ((c >> 1) == tid) v[c & 1] -= Dprev - sm.l.keyc[s];
            }
        }
        __syncthreads();

        // augment: predecessor 0 is the virtual root column holding row i
        if (tid == 0) {
            int jj = sm.l.chosen[S - 1] + 1;
            while (jj) {
                const int jn = (int)sm.l.way[jj - 1];
                sm.l.p[jj] = jn ? sm.l.p[jn] : i;
                jj = jn;
            }
        }
        __syncthreads();
    }

    if (tid == 0) {
        int preds[NT];
        for (int j = 1; j <= NQ; j++)
            if (sm.l.p[j] > 0) preds[sm.l.p[j] - 1] = j - 1;
        int order[NT];
        for (int k = 0; k < NT; k++) order[k] = k;
        for (int a = 1; a < NT; a++) {
            const int o = order[a];
            const int kv = preds[o];
            int c = a - 1;
            while (c >= 0 && preds[order[c]] > kv) { order[c + 1] = order[c]; c--; }
            order[c + 1] = o;
        }
        for (int k = 0; k < NT; k++) {
            outPred[b * NT + k] = (float)preds[order[k]];
            outTgt[b * NT + k]  = (float)order[k];
        }
    }
}

// ---------------------------------------------------------------------------
// Cost role: 32 rows per block (2 rows/warp), streams all 960 columns.
// ---------------------------------------------------------------------------
__device__ void cost_role(SmemU& sm, int cb,
    const float* __restrict__ logits, const float* __restrict__ boxes,
    const int* __restrict__ labels, const float* __restrict__ tboxes,
    float* __restrict__ C)
{
    const int tid = threadIdx.x, warp = tid >> 5, lane = tid & 31;

    for (int j = tid; j < NTT; j += NTH) {
        const float4 tb = reinterpret_cast<const float4*>(tboxes)[j];
        const float bx0 = tb.x - 0.5f * tb.z, by0 = tb.y - 0.5f * tb.w;
        const float bx1 = tb.x + 0.5f * tb.z, by1 = tb.y + 0.5f * tb.w;
        sm.c.cw[j] = tb;
        sm.c.xy[j] = make_float4(bx0, by0, bx1, by1);
        sm.c.areaB[j] = (bx1 - bx0) * (by1 - by0);
        sm.c.lab[j] = labels[j];
    }
    __syncthreads();

    const int rbase = cb * 32 + warp * 2;   // grid cost = 900 exactly

    #pragma unroll
    for (int rr = 0; rr < 2; rr++) {
        const int row = rbase + rr;
        const float* lr = logits + (size_t)row * NC;
        const float a0 = lr[lane];
        const float a1 = lr[lane + 32];
        const float a2 = (lane < NC - 64) ? lr[lane + 64] : -1e30f;
        float m = fmaxf(fmaxf(a0, a1), a2);
        #pragma unroll
        for (int o = 16; o; o >>= 1) m = fmaxf(m, __shfl_xor_sync(~0u, m, o));
        const float e0 = __expf(a0 - m);
        const float e1 = __expf(a1 - m);
        const float e2 = (lane < NC - 64) ? __expf(a2 - m) : 0.0f;
        float s = e0 + e1 + e2;
        #pragma unroll
        for (int o = 16; o; o >>= 1) s += __shfl_xor_sync(~0u, s, o);
        const float inv = __fdividef(1.0f, s);
        sm.c.sprob[warp * 2 + rr][lane]      = 1.0f - e0 * inv;
        sm.c.sprob[warp * 2 + rr][lane + 32] = 1.0f - e1 * inv;
        if (lane < NC - 64) sm.c.sprob[warp * 2 + rr][lane + 64] = 1.0f - e2 * inv;
    }
    __syncwarp();

    const float4 p0 = reinterpret_cast<const float4*>(boxes)[rbase];
    const float4 p1 = reinterpret_cast<const float4*>(boxes)[rbase + 1];
    const float ax00 = p0.x - 0.5f * p0.z, ay00 = p0.y - 0.5f * p0.w;
    const float ax01 = p0.x + 0.5f * p0.z, ay01 = p0.y + 0.5f * p0.w;
    const float arA0 = (ax01 - ax00) * (ay01 - ay00);
    const float ax10 = p1.x - 0.5f * p1.z, ay10 = p1.y - 0.5f * p1.w;
    const float ax11 = p1.x + 0.5f * p1.z, ay11 = p1.y + 0.5f * p1.w;
    const float arA1 = (ax11 - ax10) * (ay11 - ay10);

    const float* pr0 = sm.c.sprob[warp * 2];
    const float* pr1 = sm.c.sprob[warp * 2 + 1];
    float* __restrict__ c0 = C + (size_t)rbase * NTT;
    float* __restrict__ c1 = c0 + NTT;

    #pragma unroll 5
    for (int k = 0; k < 30; k++) {
        const int j = lane + 32 * k;
        const float4 X = sm.c.xy[j];
        const float4 W = sm.c.cw[j];
        const float ab = sm.c.areaB[j];
        const int lb = sm.c.lab[j];
        c0[j] = pair_cost(p0.x, p0.y, p0.z, p0.w, ax00, ay00, ax01, ay01, arA0, pr0[lb],
                          W.x, W.y, W.z, W.w, X.x, X.y, X.z, X.w, ab);
        c1[j] = pair_cost(p1.x, p1.y, p1.z, p1.w, ax10, ay10, ax11, ay11, arA1, pr1[lb],
                          W.x, W.y, W.z, W.w, X.x, X.y, X.z, X.w, ab);
    }
}

// ---------------------------------------------------------------------------
__global__ void reset_kernel() {
    if (threadIdx.x < BS) g_done[threadIdx.x] = 0;
}

__global__ __launch_bounds__(NTH) void fused_kernel(
    const float* __restrict__ logits, const float* __restrict__ boxes,
    const int* __restrict__ labels, const float* __restrict__ tboxes,
    float* __restrict__ C, float* __restrict__ outPred, float* __restrict__ outTgt)
{
    extern __shared__ __align__(16) unsigned char dynsm[];
    SmemU& sm = *reinterpret_cast<SmemU*>(dynsm);

    const int bid = blockIdx.x;
    if (bid < BS) {
        slice_role(bid, logits, boxes, labels, tboxes);
    } else if (bid < 2 * BS) {
        lsa_role(sm, bid - BS, outPred, outTgt);
    } else {
        cost_role(sm, bid - 2 * BS, logits, boxes, labels, tboxes, C);
    }
}

// ---------------------------------------------------------------------------
extern "C" void kernel_launch(void* const* d_in, const int* in_sizes, int n_in,
                              void* d_out, int out_size)
{
    const float* logits = (const float*)d_in[0];   // (32,900,91) f32
    const float* boxes  = (const float*)d_in[1];   // (32,900,4)  f32
    const int*   labels = (const int*)d_in[2];     // (32,30)     i32
    const float* tboxes = (const float*)d_in[3];   // (32,30,4)   f32

    float* out = (float*)d_out;
    float* outC    = out;                                  // 32*900*960
    float* outPred = out + (size_t)BS * NQ * NTT;          // 960
    float* outTgt  = outPred + BS * NT;                    // 960

    cudaFuncSetAttribute(fused_kernel,
                         cudaFuncAttributeMaxDynamicSharedMemorySize,
                         (int)sizeof(SmemU));

    reset_kernel<<<1, 32>>>();
    fused_kernel<<<2 * BS + (BS * NQ) / 32, NTH, sizeof(SmemU)>>>(
        logits, boxes, labels, tboxes, outC, outPred, outTgt);
}

// round 11
// speedup vs baseline: 6.6169x; 1.3684x over previous
#include <cuda_runtime.h>
#include <cuda_bf16.h>
#include <math.h>

#define BS 32
#define NQ 900
#define NC 91
#define NT 30
#define NTT (BS * NT)   // 960
#define NTH 512          // threads per block (16 warps)

// slice: g_slice[b][t][q] = C[b, q, b*NT + t]
__device__ float g_slice[BS * NT * NQ];
__device__ int   g_done[BS];

// ---------------------------------------------------------------------------
struct CostSm {
    float4 xy[NTT];            // bx0,by0,bx1,by1
    float4 cw[NTT];            // tx,ty,tw,th
    float  areaB[NTT];
    int    lab[NTT];
    float  sprob[32][NC + 1];  // (1 - prob)
};
struct LsaSm {
    float  cost[NT][NQ];       // 105.5 KB
    double u[NT + 2];
    double keyc[NT + 2];
    unsigned long long rp[2][16];
    int    chosen[NT + 2];
    int    p[NQ + 1];
    unsigned short way[NQ];
    int    jm[NT];             // greedy argmin column per row
    int    freeRows[NT];
    int    nFree;
};
union SmemU { CostSm c; LsaSm l; };

// cost = 5*l1 + (1-prob) + 2*(2 - inter/uni - uni/encl)
__device__ __forceinline__ float pair_cost(
    float cx, float cy, float w, float h,
    float ax0, float ay0, float ax1, float ay1, float areaA, float cc,
    float tx, float ty, float tw, float th,
    float bx0, float by0, float bx1, float by1, float areaB)
{
    const float l1 = fabsf(cx - tx) + fabsf(cy - ty) + fabsf(w - tw) + fabsf(h - th);
    const float iw = fmaxf(fminf(ax1, bx1) - fmaxf(ax0, bx0), 0.0f);
    const float ih = fmaxf(fminf(ay1, by1) - fmaxf(ay0, by0), 0.0f);
    const float inter = iw * ih;
    const float uni = areaA + areaB - inter;
    const float encl = (fmaxf(ax1, bx1) - fminf(ax0, bx0))
                     * (fmaxf(ay1, by1) - fminf(ay0, by0));
    return 5.0f * l1 + cc + 4.0f
         - 2.0f * __fdividef(inter, uni)
         - 2.0f * __fdividef(uni, encl);
}

__device__ __forceinline__ unsigned long long dmap(double d) {
    long long s = __double_as_longlong(d);
    return (unsigned long long)(s < 0 ? ~s : (s | 0x8000000000000000ll));
}
__device__ __forceinline__ double dunmap(unsigned long long u) {
    long long s = (u & 0x8000000000000000ull)
                ? (long long)(u & 0x7fffffffffffffffull)
                : ~(long long)u;
    return __longlong_as_double(s);
}
// pack candidate + column: key truncated at 16 low bits, idx in low 16
__device__ __forceinline__ unsigned long long packkey(double d, int j) {
    return (dmap(d) & ~0xFFFFull) | (unsigned long long)j;
}
__device__ __forceinline__ double unpackval(unsigned long long pk) {
    return dunmap(pk & ~0xFFFFull);
}

// ---------------------------------------------------------------------------
// Slice role: compute g_slice for one batch fast, then raise g_done[b].
// ---------------------------------------------------------------------------
__device__ void slice_role(int b,
    const float* __restrict__ logits, const float* __restrict__ boxes,
    const int* __restrict__ labels, const float* __restrict__ tboxes)
{
    const int tid = threadIdx.x, warp = tid >> 5, lane = tid & 31;

    int lab_t = 0;
    float tx = 0, ty = 0, tw = 0, th = 0, bx0 = 0, by0 = 0, bx1 = 0, by1 = 0, areaB = 0;
    if (lane < NT) {
        lab_t = labels[b * NT + lane];
        const float4 tb = reinterpret_cast<const float4*>(tboxes)[b * NT + lane];
        tx = tb.x; ty = tb.y; tw = tb.z; th = tb.w;
        bx0 = tx - 0.5f * tw; by0 = ty - 0.5f * th;
        bx1 = tx + 0.5f * tw; by1 = ty + 0.5f * th;
        areaB = (bx1 - bx0) * (by1 - by0);
    }

    for (int q = warp; q < NQ; q += 16) {
        const float* lr = logits + ((size_t)b * NQ + q) * NC;
        const float a0 = lr[lane];
        const float a1 = lr[lane + 32];
        const float a2 = (lane < NC - 64) ? lr[lane + 64] : -1e30f;
        float m = fmaxf(fmaxf(a0, a1), a2);
        #pragma unroll
        for (int o = 16; o; o >>= 1) m = fmaxf(m, __shfl_xor_sync(~0u, m, o));
        float s = __expf(a0 - m) + __expf(a1 - m)
                + ((lane < NC - 64) ? __expf(a2 - m) : 0.0f);
        #pragma unroll
        for (int o = 16; o; o >>= 1) s += __shfl_xor_sync(~0u, s, o);
        if (lane < NT) {
            const float cc = 1.0f - __fdividef(__expf(__ldg(&lr[lab_t]) - m), s);
            const float4 pb = reinterpret_cast<const float4*>(boxes)[b * NQ + q];
            const float ax0 = pb.x - 0.5f * pb.z, ay0 = pb.y - 0.5f * pb.w;
            const float ax1 = pb.x + 0.5f * pb.z, ay1 = pb.y + 0.5f * pb.w;
            const float areaA = (ax1 - ax0) * (ay1 - ay0);
            g_slice[((size_t)(b * NT + lane)) * NQ + q] =
                pair_cost(pb.x, pb.y, pb.z, pb.w, ax0, ay0, ax1, ay1, areaA, cc,
                          tx, ty, tw, th, bx0, by0, bx1, by1, areaB);
        }
    }
    __syncthreads();
    __threadfence();
    if (tid == 0) atomicExch(&g_done[b], 1);
}

// ---------------------------------------------------------------------------
// LSA role: JV with greedy dual init + deferred duals + packed u64 argmin.
// ---------------------------------------------------------------------------
__device__ void lsa_role(SmemU& sm, int b, float* outPred, float* outTgt)
{
    const int tid = threadIdx.x, warp = tid >> 5, lane = tid & 31;

    if (tid == 0) { while (atomicAdd(&g_done[b], 0) == 0) __nanosleep(128); }
    __syncthreads();
    __threadfence();

    const unsigned long long KINF = 0xffffffffffffffffull;
    const bool act = (tid * 2 < NQ);   // tid < 450

    // copy cost slice to shared
    {
        const float4* src = reinterpret_cast<const float4*>(g_slice + (size_t)b * NT * NQ);
        float4* dst = reinterpret_cast<float4*>(&sm.l.cost[0][0]);
        for (int idx = tid; idx < NT * NQ / 4; idx += NTH) dst[idx] = src[idx];
    }
    for (int j = tid; j < NQ; j += NTH) sm.l.p[j + 1] = 0;
    double v[2] = {0.0, 0.0};
    int par = 0;
    __syncthreads();

    // ---- greedy dual init: u[i] = row min (truncated key), argmin column ----
    for (int r = warp; r < NT; r += 16) {
        const float* crow = sm.l.cost[r];
        unsigned long long mk = KINF;
        for (int j = lane; j < NQ; j += 32)
            mk = min(mk, packkey((double)crow[j], j));
        #pragma unroll
        for (int o = 16; o; o >>= 1)
            mk = min(mk, __shfl_down_sync(~0u, mk, o));
        if (lane == 0) {
            sm.l.u[r + 1] = unpackval(mk);
            sm.l.jm[r] = (int)(mk & 0xFFFF);
        }
    }
    __syncthreads();
    if (tid == 0) {
        int nf = 0;
        for (int i = 1; i <= NT; i++) {
            const int j = sm.l.jm[i - 1];
            if (sm.l.p[j + 1] == 0) sm.l.p[j + 1] = i;
            else sm.l.freeRows[nf++] = i;
        }
        sm.l.nFree = nf;
    }
    __syncthreads();
    const int nFree = sm.l.nFree;

    // ---- augmenting phases for unassigned rows only ----
    for (int fi = 0; fi < nFree; fi++) {
        const int i = sm.l.freeRows[fi];
        unsigned long long key[2] = {KINF, KINF};
        int usedm = 0;
        int i0 = i, j0 = 0, S = 0;
        double Dprev = 0.0;

        while (true) {
            const double K = Dprev - sm.l.u[i0];
            const float* __restrict__ crow = sm.l.cost[i0 - 1];

            unsigned long long bk = KINF;
            if (act) {
                const float2 c2 = *reinterpret_cast<const float2*>(crow + 2 * tid);
                const float cv[2] = {c2.x, c2.y};
                #pragma unroll
                for (int k = 0; k < 2; k++) {
                    if (!((usedm >> k) & 1)) {
                        const double cand = ((double)cv[k] - v[k]) + K;
                        const unsigned long long pk = packkey(cand, 2 * tid + k);
                        if (pk < key[k]) {
                            key[k] = pk;
                            sm.l.way[2 * tid + k] = (unsigned short)j0;
                        }
                        bk = min(bk, key[k]);
                    }
                }
            }
            #pragma unroll
            for (int o = 16; o; o >>= 1)
                bk = min(bk, __shfl_down_sync(~0u, bk, o));
            if (lane == 0) sm.l.rp[par][warp] = bk;
            __syncthreads();                       // the ONLY barrier per step

            unsigned long long mk = (lane < 16) ? sm.l.rp[par][lane] : KINF;
            #pragma unroll
            for (int o = 8; o; o >>= 1)
                mk = min(mk, __shfl_down_sync(~0u, mk, o));
            mk = __shfl_sync(~0u, mk, 0);

            const int j1 = (int)(mk & 0xFFFF);
            Dprev = unpackval(mk);
            if (tid == 0) { sm.l.chosen[S] = j1; sm.l.keyc[S] = Dprev; }
            const int ni0 = sm.l.p[j1 + 1];        // broadcast smem read
            if (act && (j1 >> 1) == tid) usedm |= 1 << (j1 & 1);
            j0 = j1 + 1;
            S++;
            par ^= 1;
            if (ni0 == 0) break;
            i0 = ni0;
        }
        __syncthreads();   // chosen/keyc/way visible; scans finished

        // phase-end dual updates (before augment)
        if (tid == 0) {
            sm.l.u[i] += Dprev;
        } else if (tid < S) {
            const int c = sm.l.chosen[tid - 1];
            sm.l.u[sm.l.p[c + 1]] += Dprev - sm.l.keyc[tid - 1];
        }
        if (act) {
            for (int s = 0; s < S - 1; s++) {
                const int c = sm.l.chosen[s];
                if ((c >> 1) == tid) v[c & 1] -= Dprev - sm.l.keyc[s];
            }
        }
        __syncthreads();

        // augment: predecessor 0 is the virtual root column holding row i
        if (tid == 0) {
            int jj = sm.l.chosen[S - 1] + 1;
            while (jj) {
                const int jn = (int)sm.l.way[jj - 1];
                sm.l.p[jj] = jn ? sm.l.p[jn] : i;
                jj = jn;
            }
        }
        __syncthreads();
    }

    if (tid == 0) {
        int preds[NT];
        for (int j = 1; j <= NQ; j++)
            if (sm.l.p[j] > 0) preds[sm.l.p[j] - 1] = j - 1;
        int order[NT];
        for (int k = 0; k < NT; k++) order[k] = k;
        for (int a = 1; a < NT; a++) {
            const int o = order[a];
            const int kv = preds[o];
            int c = a - 1;
            while (c >= 0 && preds[order[c]] > kv) { order[c + 1] = order[c]; c--; }
            order[c + 1] = o;
        }
        for (int k = 0; k < NT; k++) {
            outPred[b * NT + k] = (float)preds[order[k]];
            outTgt[b * NT + k]  = (float)order[k];
        }
    }
}

// ---------------------------------------------------------------------------
// Cost role: 32 rows per block (2 rows/warp), streams all 960 columns.
// ---------------------------------------------------------------------------
__device__ void cost_role(SmemU& sm, int cb,
    const float* __restrict__ logits, const float* __restrict__ boxes,
    const int* __restrict__ labels, const float* __restrict__ tboxes,
    float* __restrict__ C)
{
    const int tid = threadIdx.x, warp = tid >> 5, lane = tid & 31;

    for (int j = tid; j < NTT; j += NTH) {
        const float4 tb = reinterpret_cast<const float4*>(tboxes)[j];
        const float bx0 = tb.x - 0.5f * tb.z, by0 = tb.y - 0.5f * tb.w;
        const float bx1 = tb.x + 0.5f * tb.z, by1 = tb.y + 0.5f * tb.w;
        sm.c.cw[j] = tb;
        sm.c.xy[j] = make_float4(bx0, by0, bx1, by1);
        sm.c.areaB[j] = (bx1 - bx0) * (by1 - by0);
        sm.c.lab[j] = labels[j];
    }
    __syncthreads();

    const int rbase = cb * 32 + warp * 2;   // cost grid = 900 exactly

    #pragma unroll
    for (int rr = 0; rr < 2; rr++) {
        const int row = rbase + rr;
        const float* lr = logits + (size_t)row * NC;
        const float a0 = lr[lane];
        const float a1 = lr[lane + 32];
        const float a2 = (lane < NC - 64) ? lr[lane + 64] : -1e30f;
        float m = fmaxf(fmaxf(a0, a1), a2);
        #pragma unroll
        for (int o = 16; o; o >>= 1) m = fmaxf(m, __shfl_xor_sync(~0u, m, o));
        const float e0 = __expf(a0 - m);
        const float e1 = __expf(a1 - m);
        const float e2 = (lane < NC - 64) ? __expf(a2 - m) : 0.0f;
        float s = e0 + e1 + e2;
        #pragma unroll
        for (int o = 16; o; o >>= 1) s += __shfl_xor_sync(~0u, s, o);
        const float inv = __fdividef(1.0f, s);
        sm.c.sprob[warp * 2 + rr][lane]      = 1.0f - e0 * inv;
        sm.c.sprob[warp * 2 + rr][lane + 32] = 1.0f - e1 * inv;
        if (lane < NC - 64) sm.c.sprob[warp * 2 + rr][lane + 64] = 1.0f - e2 * inv;
    }
    __syncwarp();

    const float4 p0 = reinterpret_cast<const float4*>(boxes)[rbase];
    const float4 p1 = reinterpret_cast<const float4*>(boxes)[rbase + 1];
    const float ax00 = p0.x - 0.5f * p0.z, ay00 = p0.y - 0.5f * p0.w;
    const float ax01 = p0.x + 0.5f * p0.z, ay01 = p0.y + 0.5f * p0.w;
    const float arA0 = (ax01 - ax00) * (ay01 - ay00);
    const float ax10 = p1.x - 0.5f * p1.z, ay10 = p1.y - 0.5f * p1.w;
    const float ax11 = p1.x + 0.5f * p1.z, ay11 = p1.y + 0.5f * p1.w;
    const float arA1 = (ax11 - ax10) * (ay11 - ay10);

    const float* pr0 = sm.c.sprob[warp * 2];
    const float* pr1 = sm.c.sprob[warp * 2 + 1];
    float* __restrict__ c0 = C + (size_t)rbase * NTT;
    float* __restrict__ c1 = c0 + NTT;

    #pragma unroll 5
    for (int k = 0; k < 30; k++) {
        const int j = lane + 32 * k;
        const float4 X = sm.c.xy[j];
        const float4 W = sm.c.cw[j];
        const float ab = sm.c.areaB[j];
        const int lb = sm.c.lab[j];
        c0[j] = pair_cost(p0.x, p0.y, p0.z, p0.w, ax00, ay00, ax01, ay01, arA0, pr0[lb],
                          W.x, W.y, W.z, W.w, X.x, X.y, X.z, X.w, ab);
        c1[j] = pair_cost(p1.x, p1.y, p1.z, p1.w, ax10, ay10, ax11, ay11, arA1, pr1[lb],
                          W.x, W.y, W.z, W.w, X.x, X.y, X.z, X.w, ab);
    }
}

// ---------------------------------------------------------------------------
__global__ void reset_kernel() {
    if (threadIdx.x < BS) g_done[threadIdx.x] = 0;
}

__global__ __launch_bounds__(NTH) void fused_kernel(
    const float* __restrict__ logits, const float* __restrict__ boxes,
    const int* __restrict__ labels, const float* __restrict__ tboxes,
    float* __restrict__ C, float* __restrict__ outPred, float* __restrict__ outTgt)
{
    extern __shared__ __align__(16) unsigned char dynsm[];
    SmemU& sm = *reinterpret_cast<SmemU*>(dynsm);

    const int bid = blockIdx.x;
    if (bid < BS) {
        slice_role(bid, logits, boxes, labels, tboxes);
    } else if (bid < 2 * BS) {
        lsa_role(sm, bid - BS, outPred, outTgt);
    } else {
        cost_role(sm, bid - 2 * BS, logits, boxes, labels, tboxes, C);
    }
}

// ---------------------------------------------------------------------------
extern "C" void kernel_launch(void* const* d_in, const int* in_sizes, int n_in,
                              void* d_out, int out_size)
{
    const float* logits = (const float*)d_in[0];   // (32,900,91) f32
    const float* boxes  = (const float*)d_in[1];   // (32,900,4)  f32
    const int*   labels = (const int*)d_in[2];     // (32,30)     i32
    const float* tboxes = (const float*)d_in[3];   // (32,30,4)   f32

    float* out = (float*)d_out;
    float* outC    = out;                                  // 32*900*960
    float* outPred = out + (size_t)BS * NQ * NTT;          // 960
    float* outTgt  = outPred + BS * NT;                    // 960

    cudaFuncSetAttribute(fused_kernel,
                         cudaFuncAttributeMaxDynamicSharedMemorySize,
                         (int)sizeof(SmemU));

    reset_kernel<<<1, 32>>>();
    fused_kernel<<<2 * BS + (BS * NQ) / 32, NTH, sizeof(SmemU)>>>(
        logits, boxes, labels, tboxes, outC, outPred, outTgt);
}

// round 12
// speedup vs baseline: 6.7353x; 1.0179x over previous
#include <cuda_runtime.h>
#include <cuda_bf16.h>
#include <math.h>

#define BS 32
#define NQ 900
#define NC 91
#define NT 30
#define NTT (BS * NT)   // 960
#define NTH 512          // threads per block (16 warps)

// slice: g_slice[b][t][q] = C[b, q, b*NT + t]
__device__ float g_slice[BS * NT * NQ];
__device__ int   g_done[BS];

// ---------------------------------------------------------------------------
struct CostSm {
    float4 xy[NTT];            // bx0,by0,bx1,by1
    float4 cw[NTT];            // tx,ty,tw,th
    float  areaB[NTT];
    int    lab[NTT];
    float  sprob[32][NC + 1];  // (1 - prob)
};
struct LsaSm {
    double u[NT + 2];
    double keyc[NT + 2];
    unsigned long long rp[2][16];
    int    chosen[NT + 2];
    int    p[NQ + 1];
    unsigned short way[NQ];
    int    jm[NT];
    int    freeRows[NT];
    int    nFree;
};
union SmemU { CostSm c; LsaSm l; };

// cost = 5*l1 + (1-prob) + 4 - 2*(inter*encl + uni^2)/(uni*encl)
__device__ __forceinline__ float pair_cost(
    float cx, float cy, float w, float h,
    float ax0, float ay0, float ax1, float ay1, float areaA, float cc,
    float tx, float ty, float tw, float th,
    float bx0, float by0, float bx1, float by1, float areaB)
{
    const float l1 = fabsf(cx - tx) + fabsf(cy - ty) + fabsf(w - tw) + fabsf(h - th);
    const float iw = fmaxf(fminf(ax1, bx1) - fmaxf(ax0, bx0), 0.0f);
    const float ih = fmaxf(fminf(ay1, by1) - fmaxf(ay0, by0), 0.0f);
    const float inter = iw * ih;
    const float uni = areaA + areaB - inter;
    const float encl = (fmaxf(ax1, bx1) - fminf(ax0, bx0))
                     * (fmaxf(ay1, by1) - fminf(ay0, by0));
    const float num = fmaf(inter, encl, uni * uni);
    return fmaf(5.0f, l1, cc) + 4.0f - 2.0f * __fdividef(num, uni * encl);
}

__device__ __forceinline__ unsigned long long dmap(double d) {
    long long s = __double_as_longlong(d);
    return (unsigned long long)(s < 0 ? ~s : (s | 0x8000000000000000ll));
}
__device__ __forceinline__ double dunmap(unsigned long long u) {
    long long s = (u & 0x8000000000000000ull)
                ? (long long)(u & 0x7fffffffffffffffull)
                : ~(long long)u;
    return __longlong_as_double(s);
}
// pack candidate + column: key truncated at 16 low bits, idx in low 16
__device__ __forceinline__ unsigned long long packkey(double d, int j) {
    return (dmap(d) & ~0xFFFFull) | (unsigned long long)j;
}
__device__ __forceinline__ double unpackval(unsigned long long pk) {
    return dunmap(pk & ~0xFFFFull);
}

// ---------------------------------------------------------------------------
// Slice role: compute g_slice for one batch fast, then raise g_done[b].
// ---------------------------------------------------------------------------
__device__ void slice_role(int b,
    const float* __restrict__ logits, const float* __restrict__ boxes,
    const int* __restrict__ labels, const float* __restrict__ tboxes)
{
    const int tid = threadIdx.x, warp = tid >> 5, lane = tid & 31;

    int lab_t = 0;
    float tx = 0, ty = 0, tw = 0, th = 0, bx0 = 0, by0 = 0, bx1 = 0, by1 = 0, areaB = 0;
    if (lane < NT) {
        lab_t = labels[b * NT + lane];
        const float4 tb = reinterpret_cast<const float4*>(tboxes)[b * NT + lane];
        tx = tb.x; ty = tb.y; tw = tb.z; th = tb.w;
        bx0 = tx - 0.5f * tw; by0 = ty - 0.5f * th;
        bx1 = tx + 0.5f * tw; by1 = ty + 0.5f * th;
        areaB = (bx1 - bx0) * (by1 - by0);
    }

    for (int q = warp; q < NQ; q += 16) {
        const float* lr = logits + ((size_t)b * NQ + q) * NC;
        const float a0 = lr[lane];
        const float a1 = lr[lane + 32];
        const float a2 = (lane < NC - 64) ? lr[lane + 64] : -1e30f;
        float m = fmaxf(fmaxf(a0, a1), a2);
        #pragma unroll
        for (int o = 16; o; o >>= 1) m = fmaxf(m, __shfl_xor_sync(~0u, m, o));
        float s = __expf(a0 - m) + __expf(a1 - m)
                + ((lane < NC - 64) ? __expf(a2 - m) : 0.0f);
        #pragma unroll
        for (int o = 16; o; o >>= 1) s += __shfl_xor_sync(~0u, s, o);
        if (lane < NT) {
            const float cc = 1.0f - __fdividef(__expf(__ldg(&lr[lab_t]) - m), s);
            const float4 pb = reinterpret_cast<const float4*>(boxes)[b * NQ + q];
            const float ax0 = pb.x - 0.5f * pb.z, ay0 = pb.y - 0.5f * pb.w;
            const float ax1 = pb.x + 0.5f * pb.z, ay1 = pb.y + 0.5f * pb.w;
            const float areaA = (ax1 - ax0) * (ay1 - ay0);
            g_slice[((size_t)(b * NT + lane)) * NQ + q] =
                pair_cost(pb.x, pb.y, pb.z, pb.w, ax0, ay0, ax1, ay1, areaA, cc,
                          tx, ty, tw, th, bx0, by0, bx1, by1, areaB);
        }
    }
    __syncthreads();
    __threadfence();
    if (tid == 0) atomicExch(&g_done[b], 1);
}

// ---------------------------------------------------------------------------
// LSA role: JV, greedy dual init, deferred duals, packed u64 argmin.
// Cost rows read from L2 (g_slice); smem footprint is small.
// ---------------------------------------------------------------------------
__device__ void lsa_role(SmemU& sm, int b, float* outPred, float* outTgt)
{
    const int tid = threadIdx.x, warp = tid >> 5, lane = tid & 31;

    if (tid == 0) { while (atomicAdd(&g_done[b], 0) == 0) __nanosleep(128); }
    __syncthreads();
    __threadfence();

    const unsigned long long KINF = 0xffffffffffffffffull;
    const bool act = (tid * 2 < NQ);   // tid < 450
    const float* __restrict__ cost = g_slice + (size_t)b * NT * NQ;

    for (int j = tid; j < NQ; j += NTH) sm.l.p[j + 1] = 0;
    double v[2] = {0.0, 0.0};
    int par = 0;
    __syncthreads();

    // ---- greedy dual init: u[i] = row min (truncated key), argmin column ----
    for (int r = warp; r < NT; r += 16) {
        const float* crow = cost + (size_t)r * NQ;
        unsigned long long mk = KINF;
        for (int j = lane; j < NQ; j += 32)
            mk = min(mk, packkey((double)__ldg(&crow[j]), j));
        #pragma unroll
        for (int o = 16; o; o >>= 1)
            mk = min(mk, __shfl_down_sync(~0u, mk, o));
        if (lane == 0) {
            sm.l.u[r + 1] = unpackval(mk);
            sm.l.jm[r] = (int)(mk & 0xFFFF);
        }
    }
    __syncthreads();
    if (tid == 0) {
        int nf = 0;
        for (int i = 1; i <= NT; i++) {
            const int j = sm.l.jm[i - 1];
            if (sm.l.p[j + 1] == 0) sm.l.p[j + 1] = i;
            else sm.l.freeRows[nf++] = i;
        }
        sm.l.nFree = nf;
    }
    __syncthreads();
    const int nFree = sm.l.nFree;

    // ---- augmenting phases for unassigned rows only ----
    for (int fi = 0; fi < nFree; fi++) {
        const int i = sm.l.freeRows[fi];
        unsigned long long key[2] = {KINF, KINF};
        int usedm = 0;
        int i0 = i, j0 = 0, S = 0;
        double Dprev = 0.0;

        while (true) {
            const double K = Dprev - sm.l.u[i0];
            const float* __restrict__ crow = cost + (size_t)(i0 - 1) * NQ;

            unsigned long long bk = KINF;
            if (act) {
                const float2 c2 = __ldg(reinterpret_cast<const float2*>(crow + 2 * tid));
                const float cv[2] = {c2.x, c2.y};
                #pragma unroll
                for (int k = 0; k < 2; k++) {
                    if (!((usedm >> k) & 1)) {
                        const double cand = ((double)cv[k] - v[k]) + K;
                        const unsigned long long pk = packkey(cand, 2 * tid + k);
                        if (pk < key[k]) {
                            key[k] = pk;
                            sm.l.way[2 * tid + k] = (unsigned short)j0;
                        }
                        bk = min(bk, key[k]);
                    }
                }
            }
            #pragma unroll
            for (int o = 16; o; o >>= 1)
                bk = min(bk, __shfl_down_sync(~0u, bk, o));
            if (lane == 0) sm.l.rp[par][warp] = bk;
            __syncthreads();                       // the ONLY barrier per step

            unsigned long long mk = (lane < 16) ? sm.l.rp[par][lane] : KINF;
            #pragma unroll
            for (int o = 8; o; o >>= 1)
                mk = min(mk, __shfl_down_sync(~0u, mk, o));
            mk = __shfl_sync(~0u, mk, 0);

            const int j1 = (int)(mk & 0xFFFF);
            Dprev = unpackval(mk);
            if (tid == 0) { sm.l.chosen[S] = j1; sm.l.keyc[S] = Dprev; }
            const int ni0 = sm.l.p[j1 + 1];        // broadcast smem read
            if (act && (j1 >> 1) == tid) usedm |= 1 << (j1 & 1);
            j0 = j1 + 1;
            S++;
            par ^= 1;
            if (ni0 == 0) break;
            i0 = ni0;
        }
        __syncthreads();   // chosen/keyc/way visible; scans finished

        // phase-end dual updates (before augment)
        if (tid == 0) {
            sm.l.u[i] += Dprev;
        } else if (tid < S) {
            const int c = sm.l.chosen[tid - 1];
            sm.l.u[sm.l.p[c + 1]] += Dprev - sm.l.keyc[tid - 1];
        }
        if (act) {
            for (int s = 0; s < S - 1; s++) {
                const int c = sm.l.chosen[s];
                if ((c >> 1) == tid) v[c & 1] -= Dprev - sm.l.keyc[s];
            }
        }
        __syncthreads();

        // augment: predecessor 0 is the virtual root column holding row i
        if (tid == 0) {
            int jj = sm.l.chosen[S - 1] + 1;
            while (jj) {
                const int jn = (int)sm.l.way[jj - 1];
                sm.l.p[jj] = jn ? sm.l.p[jn] : i;
                jj = jn;
            }
        }
        __syncthreads();
    }

    if (tid == 0) {
        int preds[NT];
        for (int j = 1; j <= NQ; j++)
            if (sm.l.p[j] > 0) preds[sm.l.p[j] - 1] = j - 1;
        int order[NT];
        for (int k = 0; k < NT; k++) order[k] = k;
        for (int a = 1; a < NT; a++) {
            const int o = order[a];
            const int kv = preds[o];
            int c = a - 1;
            while (c >= 0 && preds[order[c]] > kv) { order[c + 1] = order[c]; c--; }
            order[c + 1] = o;
        }
        for (int k = 0; k < NT; k++) {
            outPred[b * NT + k] = (float)preds[order[k]];
            outTgt[b * NT + k]  = (float)order[k];
        }
    }
}

// ---------------------------------------------------------------------------
// Cost role: 32 rows per block (2 rows/warp), streams all 960 columns.
// ---------------------------------------------------------------------------
__device__ void cost_role(SmemU& sm, int cb,
    const float* __restrict__ logits, const float* __restrict__ boxes,
    const int* __restrict__ labels, const float* __restrict__ tboxes,
    float* __restrict__ C)
{
    const int tid = threadIdx.x, warp = tid >> 5, lane = tid & 31;

    for (int j = tid; j < NTT; j += NTH) {
        const float4 tb = reinterpret_cast<const float4*>(tboxes)[j];
        const float bx0 = tb.x - 0.5f * tb.z, by0 = tb.y - 0.5f * tb.w;
        const float bx1 = tb.x + 0.5f * tb.z, by1 = tb.y + 0.5f * tb.w;
        sm.c.cw[j] = tb;
        sm.c.xy[j] = make_float4(bx0, by0, bx1, by1);
        sm.c.areaB[j] = (bx1 - bx0) * (by1 - by0);
        sm.c.lab[j] = labels[j];
    }
    __syncthreads();

    const int rbase = cb * 32 + warp * 2;   // cost grid = 900 exactly

    #pragma unroll
    for (int rr = 0; rr < 2; rr++) {
        const int row = rbase + rr;
        const float* lr = logits + (size_t)row * NC;
        const float a0 = lr[lane];
        const float a1 = lr[lane + 32];
        const float a2 = (lane < NC - 64) ? lr[lane + 64] : -1e30f;
        float m = fmaxf(fmaxf(a0, a1), a2);
        #pragma unroll
        for (int o = 16; o; o >>= 1) m = fmaxf(m, __shfl_xor_sync(~0u, m, o));
        const float e0 = __expf(a0 - m);
        const float e1 = __expf(a1 - m);
        const float e2 = (lane < NC - 64) ? __expf(a2 - m) : 0.0f;
        float s = e0 + e1 + e2;
        #pragma unroll
        for (int o = 16; o; o >>= 1) s += __shfl_xor_sync(~0u, s, o);
        const float inv = __fdividef(1.0f, s);
        sm.c.sprob[warp * 2 + rr][lane]      = 1.0f - e0 * inv;
        sm.c.sprob[warp * 2 + rr][lane + 32] = 1.0f - e1 * inv;
        if (lane < NC - 64) sm.c.sprob[warp * 2 + rr][lane + 64] = 1.0f - e2 * inv;
    }
    __syncwarp();

    const float4 p0 = reinterpret_cast<const float4*>(boxes)[rbase];
    const float4 p1 = reinterpret_cast<const float4*>(boxes)[rbase + 1];
    const float ax00 = p0.x - 0.5f * p0.z, ay00 = p0.y - 0.5f * p0.w;
    const float ax01 = p0.x + 0.5f * p0.z, ay01 = p0.y + 0.5f * p0.w;
    const float arA0 = (ax01 - ax00) * (ay01 - ay00);
    const float ax10 = p1.x - 0.5f * p1.z, ay10 = p1.y - 0.5f * p1.w;
    const float ax11 = p1.x + 0.5f * p1.z, ay11 = p1.y + 0.5f * p1.w;
    const float arA1 = (ax11 - ax10) * (ay11 - ay10);

    const float* pr0 = sm.c.sprob[warp * 2];
    const float* pr1 = sm.c.sprob[warp * 2 + 1];
    float* __restrict__ c0 = C + (size_t)rbase * NTT;
    float* __restrict__ c1 = c0 + NTT;

    #pragma unroll 5
    for (int k = 0; k < 30; k++) {
        const int j = lane + 32 * k;
        const float4 X = sm.c.xy[j];
        const float4 W = sm.c.cw[j];
        const float ab = sm.c.areaB[j];
        const int lb = sm.c.lab[j];
        c0[j] = pair_cost(p0.x, p0.y, p0.z, p0.w, ax00, ay00, ax01, ay01, arA0, pr0[lb],
                          W.x, W.y, W.z, W.w, X.x, X.y, X.z, X.w, ab);
        c1[j] = pair_cost(p1.x, p1.y, p1.z, p1.w, ax10, ay10, ax11, ay11, arA1, pr1[lb],
                          W.x, W.y, W.z, W.w, X.x, X.y, X.z, X.w, ab);
    }
}

// ---------------------------------------------------------------------------
__global__ void reset_kernel() {
    if (threadIdx.x < BS) g_done[threadIdx.x] = 0;
}

__global__ __launch_bounds__(NTH, 3) void fused_kernel(
    const float* __restrict__ logits, const float* __restrict__ boxes,
    const int* __restrict__ labels, const float* __restrict__ tboxes,
    float* __restrict__ C, float* __restrict__ outPred, float* __restrict__ outTgt)
{
    extern __shared__ __align__(16) unsigned char dynsm[];
    SmemU& sm = *reinterpret_cast<SmemU*>(dynsm);

    const int bid = blockIdx.x;
    if (bid < BS) {
        slice_role(bid, logits, boxes, labels, tboxes);
    } else if (bid < 2 * BS) {
        lsa_role(sm, bid - BS, outPred, outTgt);
    } else {
        cost_role(sm, bid - 2 * BS, logits, boxes, labels, tboxes, C);
    }
}

// ---------------------------------------------------------------------------
extern "C" void kernel_launch(void* const* d_in, const int* in_sizes, int n_in,
                              void* d_out, int out_size)
{
    const float* logits = (const float*)d_in[0];   // (32,900,91) f32
    const float* boxes  = (const float*)d_in[1];   // (32,900,4)  f32
    const int*   labels = (const int*)d_in[2];     // (32,30)     i32
    const float* tboxes = (const float*)d_in[3];   // (32,30,4)   f32

    float* out = (float*)d_out;
    float* outC    = out;                                  // 32*900*960
    float* outPred = out + (size_t)BS * NQ * NTT;          // 960
    float* outTgt  = outPred + BS * NT;                    // 960

    cudaFuncSetAttribute(fused_kernel,
                         cudaFuncAttributeMaxDynamicSharedMemorySize,
                         (int)sizeof(SmemU));

    reset_kernel<<<1, 32>>>();
    fused_kernel<<<2 * BS + (BS * NQ) / 32, NTH, sizeof(SmemU)>>>(
        logits, boxes, labels, tboxes, outC, outPred, outTgt);
}